// round 10
// baseline (speedup 1.0000x reference)
#include <cuda_runtime.h>
#include <cuda_bf16.h>
#include <cstdint>
#include <math.h>

// ---------------------------------------------------------------------------
// Problem constants
// ---------------------------------------------------------------------------
#define BATCH      4
#define SEQ        1024
#define DEMB       8192
#define NHEAD      8
#define DKV        256
#define QKVDIM     (NHEAD * DKV)          // 2048
#define TOK_TOTAL  (BATCH * SEQ)          // 4096
#define PLANE      ((long)SEQ * DEMB)

// ---------------------------------------------------------------------------
// Scratch (static device allocations — no cudaMalloc allowed)
// ---------------------------------------------------------------------------
__device__ __align__(256) float  g_X[(long)BATCH * SEQ * DEMB];
__device__ __align__(256) float  g_V[(long)BATCH * SEQ * QKVDIM];
__device__ __align__(256) float  g_S[(long)BATCH * NHEAD * SEQ * SEQ];
__device__ __align__(256) float  g_Z[(long)BATCH * SEQ * QKVDIM];
__device__ __align__(256) float  g_O[(long)BATCH * SEQ * DEMB];
__device__ double g_part[BATCH * 1024 * 2];
__device__ double g_mean[BATCH];
__device__ double g_rstd[BATCH];
__device__ float    g_scales[4];   // 0:X 1:Wqkv 2:Wo 3:Z
__device__ unsigned g_amax[4];

// int8 hi/lo fixed-point planes
__device__ __align__(256) int8_t g_X1[(long)BATCH * SEQ * DEMB];
__device__ __align__(256) int8_t g_X0[(long)BATCH * SEQ * DEMB];
__device__ __align__(256) int8_t g_W1[(long)3 * QKVDIM * DEMB];
__device__ __align__(256) int8_t g_W0[(long)3 * QKVDIM * DEMB];
__device__ __align__(256) int8_t g_Wo1[(long)DEMB * QKVDIM];
__device__ __align__(256) int8_t g_Wo0[(long)DEMB * QKVDIM];
__device__ __align__(256) int8_t g_Z1[(long)BATCH * SEQ * QKVDIM];
__device__ __align__(256) int8_t g_Z0[(long)BATCH * SEQ * QKVDIM];

// bf16 hi/lo split operands (attention path, unchanged round-7 math)
__device__ __align__(256) __nv_bfloat16 g_Qh[(long)BATCH * SEQ * QKVDIM];
__device__ __align__(256) __nv_bfloat16 g_Ql[(long)BATCH * SEQ * QKVDIM];
__device__ __align__(256) __nv_bfloat16 g_Kh[(long)BATCH * SEQ * QKVDIM];
__device__ __align__(256) __nv_bfloat16 g_Kl[(long)BATCH * SEQ * QKVDIM];
__device__ __align__(256) __nv_bfloat16 g_Vth[(long)BATCH * NHEAD * DKV * SEQ];
__device__ __align__(256) __nv_bfloat16 g_Vtl[(long)BATCH * NHEAD * DKV * SEQ];
__device__ __align__(256) __nv_bfloat16 g_Ph[(long)BATCH * NHEAD * SEQ * SEQ];
__device__ __align__(256) __nv_bfloat16 g_Pl[(long)BATCH * NHEAD * SEQ * SEQ];

// ---------------------------------------------------------------------------
// PTX helpers
// ---------------------------------------------------------------------------
__device__ __forceinline__ uint32_t smem_u32(const void* p) {
    uint32_t a;
    asm("{ .reg .u64 t; cvta.to.shared.u64 t, %1; cvt.u32.u64 %0, t; }"
        : "=r"(a) : "l"(p));
    return a;
}
__device__ __forceinline__ void cpasync16(uint32_t dst, const void* src) {
    asm volatile("cp.async.cg.shared.global [%0], [%1], 16;" :: "r"(dst), "l"(src));
}
__device__ __forceinline__ void cp_commit() {
    asm volatile("cp.async.commit_group;" ::: "memory");
}
template <int N> __device__ __forceinline__ void cp_wait() {
    asm volatile("cp.async.wait_group %0;" :: "n"(N) : "memory");
}
__device__ __forceinline__ void ldsm4(uint32_t* r, uint32_t addr) {
    asm volatile("ldmatrix.sync.aligned.m8n8.x4.shared.b16 {%0,%1,%2,%3}, [%4];"
                 : "=r"(r[0]), "=r"(r[1]), "=r"(r[2]), "=r"(r[3]) : "r"(addr));
}
__device__ __forceinline__ void ldsm2(uint32_t* r, uint32_t addr) {
    asm volatile("ldmatrix.sync.aligned.m8n8.x2.shared.b16 {%0,%1}, [%2];"
                 : "=r"(r[0]), "=r"(r[1]) : "r"(addr));
}
__device__ __forceinline__ void mma16816(float* c, const uint32_t* a, const uint32_t* b) {
    asm volatile(
        "mma.sync.aligned.m16n8k16.row.col.f32.bf16.bf16.f32 "
        "{%0,%1,%2,%3}, {%4,%5,%6,%7}, {%8,%9}, {%0,%1,%2,%3};"
        : "+f"(c[0]), "+f"(c[1]), "+f"(c[2]), "+f"(c[3])
        : "r"(a[0]), "r"(a[1]), "r"(a[2]), "r"(a[3]), "r"(b[0]), "r"(b[1]));
}
__device__ __forceinline__ void imma16832(int* c, const uint32_t* a, const uint32_t* b) {
    asm volatile(
        "mma.sync.aligned.m16n8k32.row.col.s32.s8.s8.s32 "
        "{%0,%1,%2,%3}, {%4,%5,%6,%7}, {%8,%9}, {%0,%1,%2,%3};"
        : "+r"(c[0]), "+r"(c[1]), "+r"(c[2]), "+r"(c[3])
        : "r"(a[0]), "r"(a[1]), "r"(a[2]), "r"(a[3]), "r"(b[0]), "r"(b[1]));
}
__device__ __forceinline__ __nv_bfloat162 split_hi2(float x, float y) {
    __nv_bfloat162 h;
    h.x = __float2bfloat16(x); h.y = __float2bfloat16(y);
    return h;
}
__device__ __forceinline__ __nv_bfloat162 split_lo2(float x, float y, __nv_bfloat162 h) {
    __nv_bfloat162 l;
    l.x = __float2bfloat16(x - __bfloat162float(h.x));
    l.y = __float2bfloat16(y - __bfloat162float(h.y));
    return l;
}
__device__ __forceinline__ void quant16(float v, float inv_s, int8_t& q1, int8_t& q0) {
    int q = __float2int_rn(v * inv_s);
    q = max(-32512, min(32512, q));
    int h = (q + 128) >> 8;
    q1 = (int8_t)h;
    q0 = (int8_t)(q - (h << 8));
}

// ---------------------------------------------------------------------------
// int8 fixed-point split GEMM on mma.sync.m16n8k32.s8 (IMMA).
// A = sA*(A1*256 + A0), B likewise. acc = sA*sB*(65536*A1B1 + 256*(A1B0+A0B1)).
// A*: [M,K] s8 row-major. B*: [N,K] s8 row-major. Tile 128x128, K-chunk 128,
// 3-stage cp.async pipeline, 128B rows with XOR-16B swizzle (round-5 geometry).
// mode 0: Cf fp32 (+D residual). mode 1 (fused QKV): col segment col0>>11:
//   0 -> Ch/Cl (Q bf16 split), 1 -> C2h/C2l (K), 2 -> Cf (V fp32); ldc=2048.
// ---------------------------------------------------------------------------
#define IKC    128
#define ITILE  16384                      // 128 rows x 128 bytes
#define ISTG   (4 * ITILE)                // A1, A0, B1, B0
#define INST   3
#define ISMEM  (INST * ISTG)              // 196608

__global__ __launch_bounds__(256, 1)
void imma_gemm(const int8_t* __restrict__ A1, const int8_t* __restrict__ A0, int lda,
               const int8_t* __restrict__ B1, const int8_t* __restrict__ B0, int ldb,
               float* __restrict__ Cf,
               __nv_bfloat16* __restrict__ Ch, __nv_bfloat16* __restrict__ Cl,
               __nv_bfloat16* __restrict__ C2h, __nv_bfloat16* __restrict__ C2l,
               int ldc, const float* __restrict__ D,
               int saIdx, int sbIdx, int K, int mode)
{
    extern __shared__ __align__(128) char dsm_raw[];
    const uint32_t dsm0 = smem_u32(dsm_raw);

    const int tid  = threadIdx.x;
    const int lane = tid & 31;
    const int wid  = tid >> 5;
    const int wm   = wid & 1;
    const int wn   = wid >> 1;

    // grouped rasterization: 8 M-tiles per stripe
    int pid_m, pid_n;
    {
        const int ntm = gridDim.y, ntn = gridDim.x;
        const int lin = blockIdx.y * ntn + blockIdx.x;
        const int G = 8;
        const int width = G * ntn;
        const int grp = lin / width;
        const int rem = lin - grp * width;
        const int m0  = grp * G;
        const int gsz = (ntm - m0 < G) ? (ntm - m0) : G;
        pid_m = m0 + rem % gsz;
        pid_n = rem / gsz;
    }
    const int row0 = pid_m * 128;
    const int col0 = pid_n * 128;

    // cp.async geometry: 1024 16B-chunks per tile; 4 per thread per tile
    int rr[4], cc[4]; uint32_t swo[4];
    #pragma unroll
    for (int j = 0; j < 4; j++) {
        int idx = tid + j * 256;
        rr[j] = idx >> 3;
        cc[j] = idx & 7;
        swo[j] = (uint32_t)(rr[j] * 128 + ((cc[j] ^ (rr[j] & 7)) << 4));
    }
    const int8_t* tp[4] = {A1, A0, B1, B0};
    const int nk = K / IKC;

    auto load_stage = [&](int s, int k0) {
        const uint32_t sb = dsm0 + s * ISTG;
        #pragma unroll
        for (int t = 0; t < 4; t++) {
            const int8_t* g = tp[t];
            const long ld = (t < 2) ? lda : ldb;
            const int  rb = (t < 2) ? row0 : col0;
            const uint32_t tb = sb + t * ITILE;
            #pragma unroll
            for (int j = 0; j < 4; j++)
                cpasync16(tb + swo[j], g + (long)(rb + rr[j]) * ld + k0 + cc[j] * 16);
        }
        cp_commit();
    };

    // ldsm lane geometry (identical A/B form; rows of 128B)
    const int l7  = lane & 7;
    const int sel = (lane >> 4) & 1;
    const uint32_t aBase = (uint32_t)((wm * 64 + l7 + ((lane >> 3) & 1) * 8) * 128);
    const uint32_t bBase = (uint32_t)((wn * 32 + l7 + ((lane >> 3) & 1) * 8) * 128);

    int acc1[4][4][4], acc2[4][4][4];
    #pragma unroll
    for (int mt = 0; mt < 4; mt++)
        #pragma unroll
        for (int nt = 0; nt < 4; nt++)
            #pragma unroll
            for (int q = 0; q < 4; q++) { acc1[mt][nt][q] = 0; acc2[mt][nt][q] = 0; }

    load_stage(0, 0);
    load_stage(1, IKC);

    for (int i = 0; i < nk; ++i) {
        const int s = i % INST;
        if (i + 1 < nk) cp_wait<1>(); else cp_wait<0>();
        __syncthreads();
        if (i + 2 < nk) load_stage((i + 2) % INST, (i + 2) * IKC);

        const uint32_t sb = dsm0 + s * ISTG;
        #pragma unroll
        for (int ks = 0; ks < 4; ++ks) {
            const uint32_t ksw = (uint32_t)(((2 * ks + sel) ^ l7) << 4);
            uint32_t a1[4][4], a0[4][4], b1[4][2], b0[4][2];
            #pragma unroll
            for (int mt = 0; mt < 4; mt++) {
                const uint32_t ad = sb + aBase + mt * 2048 + ksw;
                ldsm4(a1[mt], ad);               // OFF_A1 = 0
                ldsm4(a0[mt], ad + ITILE);       // OFF_A0
            }
            #pragma unroll
            for (int p = 0; p < 2; p++) {
                const uint32_t bd = sb + bBase + p * 2048 + ksw;
                uint32_t t1[4], t0[4];
                ldsm4(t1, bd + 2 * ITILE);       // OFF_B1
                ldsm4(t0, bd + 3 * ITILE);       // OFF_B0
                b1[2*p][0] = t1[0]; b1[2*p][1] = t1[2];
                b1[2*p+1][0] = t1[1]; b1[2*p+1][1] = t1[3];
                b0[2*p][0] = t0[0]; b0[2*p][1] = t0[2];
                b0[2*p+1][0] = t0[1]; b0[2*p+1][1] = t0[3];
            }
            #pragma unroll
            for (int mt = 0; mt < 4; mt++)
                #pragma unroll
                for (int nt = 0; nt < 4; nt++) {
                    imma16832(acc1[mt][nt], a1[mt], b1[nt]);
                    imma16832(acc2[mt][nt], a1[mt], b0[nt]);
                    imma16832(acc2[mt][nt], a0[mt], b1[nt]);
                }
        }
        __syncthreads();
    }

    // ---- epilogue
    const float sc = g_scales[saIdx] * g_scales[sbIdx];
    float* cf = Cf;
    __nv_bfloat16 *ch = Ch, *cl = Cl;
    int cbase = col0;
    if (mode) {
        const int seg = col0 >> 11;
        cbase = col0 & 2047;
        if (seg == 0)      { cf = nullptr; ch = Ch;  cl = Cl;  }
        else if (seg == 1) { cf = nullptr; ch = C2h; cl = C2l; }
        else               { ch = nullptr; cl = nullptr; }
    }
    const float* dp = D;

    const int cg = lane >> 2, tg = lane & 3;
    #pragma unroll
    for (int mt = 0; mt < 4; mt++) {
        #pragma unroll
        for (int nt = 0; nt < 4; nt++) {
            const int r = row0 + wm * 64 + mt * 16 + cg;
            const int c = cbase + wn * 32 + nt * 8 + tg * 2;
            const long o0 = (long)r * ldc + c;
            const long o1 = (long)(r + 8) * ldc + c;
            float2 v0, v1;
            v0.x = sc * (65536.f * (float)acc1[mt][nt][0] + 256.f * (float)acc2[mt][nt][0]);
            v0.y = sc * (65536.f * (float)acc1[mt][nt][1] + 256.f * (float)acc2[mt][nt][1]);
            v1.x = sc * (65536.f * (float)acc1[mt][nt][2] + 256.f * (float)acc2[mt][nt][2]);
            v1.y = sc * (65536.f * (float)acc1[mt][nt][3] + 256.f * (float)acc2[mt][nt][3]);
            if (dp) {
                float2 d0 = *(const float2*)(dp + o0);
                float2 d1 = *(const float2*)(dp + o1);
                v0.x += d0.x; v0.y += d0.y; v1.x += d1.x; v1.y += d1.y;
            }
            if (cf) {
                *(float2*)(cf + o0) = v0;
                *(float2*)(cf + o1) = v1;
            }
            if (ch) {
                __nv_bfloat162 h0 = split_hi2(v0.x, v0.y);
                __nv_bfloat162 h1 = split_hi2(v1.x, v1.y);
                *(__nv_bfloat162*)(ch + o0) = h0;
                *(__nv_bfloat162*)(ch + o1) = h1;
                *(__nv_bfloat162*)(cl + o0) = split_lo2(v0.x, v0.y, h0);
                *(__nv_bfloat162*)(cl + o1) = split_lo2(v1.x, v1.y, h1);
            }
        }
    }
}

// ---------------------------------------------------------------------------
// Split-precision bf16 GEMM (round-7 proven config: 128x128, KC=64, 3-stage).
// acc = alpha * (Ah*Bh^T + Ah*Bl^T + Al*Bh^T). Optional fp32 out + amax,
// used for scores (S) and PV (Z + amax for Z quantization).
// ---------------------------------------------------------------------------
#define KC      64
#define TILE_B  16384
#define STG_B   (4 * TILE_B)
#define NSTAGE  3
#define SMEM_DYN (NSTAGE * STG_B)         // 196608

__global__ __launch_bounds__(256, 1)
void mma_gemm(const __nv_bfloat16* __restrict__ Ah, const __nv_bfloat16* __restrict__ Al,
              int lda, long sAo, long sAi,
              const __nv_bfloat16* __restrict__ Bh, const __nv_bfloat16* __restrict__ Bl,
              int ldb, long sBo, long sBi,
              float* __restrict__ Cf,
              __nv_bfloat16* __restrict__ Ch, __nv_bfloat16* __restrict__ Cl,
              int ldc, long sCo, long sCi,
              int doAmax, int K, int inner, float alpha)
{
    extern __shared__ __align__(128) char dsm_raw[];
    const uint32_t dsm0 = smem_u32(dsm_raw);

    const int tid  = threadIdx.x;
    const int lane = tid & 31;
    const int wid  = tid >> 5;
    const int wm   = wid & 1;
    const int wn   = wid >> 1;

    const int z  = blockIdx.z;
    const int zo = z / inner, zi = z - zo * inner;
    Ah += zo * sAo + zi * sAi;  Al += zo * sAo + zi * sAi;
    Bh += zo * sBo + zi * sBi;  Bl += zo * sBo + zi * sBi;
    const long coff = zo * sCo + zi * sCi;

    int pid_m, pid_n;
    {
        const int ntm = gridDim.y, ntn = gridDim.x;
        const int lin = blockIdx.y * ntn + blockIdx.x;
        const int G = 8;
        const int width = G * ntn;
        const int grp = lin / width;
        const int rem = lin - grp * width;
        const int m0  = grp * G;
        const int gsz = (ntm - m0 < G) ? (ntm - m0) : G;
        pid_m = m0 + rem % gsz;
        pid_n = rem / gsz;
    }
    const int row0 = pid_m * 128;
    const int col0 = pid_n * 128;

    int rr[4], cc[4]; uint32_t swo[4];
    #pragma unroll
    for (int j = 0; j < 4; j++) {
        int idx = tid + j * 256;
        rr[j] = idx >> 3;
        cc[j] = idx & 7;
        swo[j] = (uint32_t)(rr[j] * 128 + ((cc[j] ^ (rr[j] & 7)) << 4));
    }
    const __nv_bfloat16* tp[4] = {Ah, Al, Bh, Bl};
    const int nk = K / KC;

    auto load_stage = [&](int s, int k0) {
        const uint32_t sb = dsm0 + s * STG_B;
        #pragma unroll
        for (int t = 0; t < 4; t++) {
            const __nv_bfloat16* g = tp[t];
            const long ld = (t < 2) ? lda : ldb;
            const int  rb = (t < 2) ? row0 : col0;
            const uint32_t tb = sb + t * TILE_B;
            #pragma unroll
            for (int j = 0; j < 4; j++)
                cpasync16(tb + swo[j], g + (long)(rb + rr[j]) * ld + k0 + cc[j] * 8);
        }
        cp_commit();
    };

    const int l7   = lane & 7;
    const int aSel = (lane >> 4) & 1;
    const int bSel = (lane >> 3) & 1;
    const uint32_t aRowOff = (uint32_t)((wm * 64 + l7 + ((lane >> 3) & 1) * 8) * 128);
    const uint32_t bRowOff = (uint32_t)((wn * 32 + l7) * 128);

    float acc[4][4][4];
    #pragma unroll
    for (int mt = 0; mt < 4; mt++)
        #pragma unroll
        for (int nt = 0; nt < 4; nt++)
            #pragma unroll
            for (int q = 0; q < 4; q++) acc[mt][nt][q] = 0.f;

    load_stage(0, 0);
    load_stage(1, KC);

    for (int i = 0; i < nk; ++i) {
        const int s = i % NSTAGE;
        if (i + 1 < nk) cp_wait<1>(); else cp_wait<0>();
        __syncthreads();
        if (i + 2 < nk) load_stage((i + 2) % NSTAGE, (i + 2) * KC);

        const uint32_t sb = dsm0 + s * STG_B;
        #pragma unroll
        for (int ks = 0; ks < 4; ++ks) {
            uint32_t ah[4][4], al[4][4], bh[4][2], bl[4][2];
            const uint32_t asw = (uint32_t)(((2 * ks + aSel) ^ l7) << 4);
            const uint32_t bsw = (uint32_t)(((2 * ks + bSel) ^ l7) << 4);
            #pragma unroll
            for (int mt = 0; mt < 4; mt++) {
                uint32_t ad = sb + aRowOff + mt * 2048 + asw;
                ldsm4(ah[mt], ad);
                ldsm4(al[mt], ad + TILE_B);
            }
            #pragma unroll
            for (int nt = 0; nt < 4; nt++) {
                uint32_t bd = sb + 2 * TILE_B + bRowOff + nt * 1024 + bsw;
                ldsm2(bh[nt], bd);
                ldsm2(bl[nt], bd + TILE_B);
            }
            #pragma unroll
            for (int mt = 0; mt < 4; mt++)
                #pragma unroll
                for (int nt = 0; nt < 4; nt++) {
                    mma16816(acc[mt][nt], ah[mt], bh[nt]);
                    mma16816(acc[mt][nt], ah[mt], bl[nt]);
                    mma16816(acc[mt][nt], al[mt], bh[nt]);
                }
        }
        __syncthreads();
    }

    float* cf = Cf ? Cf + coff : (float*)0;
    __nv_bfloat16* ch = Ch ? Ch + coff : (__nv_bfloat16*)0;
    __nv_bfloat16* cl = Ch ? Cl + coff : (__nv_bfloat16*)0;

    float amax = 0.f;
    const int cg = lane >> 2, tg = lane & 3;
    #pragma unroll
    for (int mt = 0; mt < 4; mt++) {
        #pragma unroll
        for (int nt = 0; nt < 4; nt++) {
            const int r = row0 + wm * 64 + mt * 16 + cg;
            const int c = col0 + wn * 32 + nt * 8 + tg * 2;
            const long o0 = (long)r * ldc + c;
            const long o1 = (long)(r + 8) * ldc + c;
            float2 v0, v1;
            v0.x = acc[mt][nt][0] * alpha; v0.y = acc[mt][nt][1] * alpha;
            v1.x = acc[mt][nt][2] * alpha; v1.y = acc[mt][nt][3] * alpha;
            if (doAmax) {
                amax = fmaxf(amax, fmaxf(fmaxf(fabsf(v0.x), fabsf(v0.y)),
                                         fmaxf(fabsf(v1.x), fabsf(v1.y))));
            }
            if (cf) {
                *(float2*)(cf + o0) = v0;
                *(float2*)(cf + o1) = v1;
            }
            if (ch) {
                __nv_bfloat162 h0 = split_hi2(v0.x, v0.y);
                __nv_bfloat162 h1 = split_hi2(v1.x, v1.y);
                *(__nv_bfloat162*)(ch + o0) = h0;
                *(__nv_bfloat162*)(ch + o1) = h1;
                *(__nv_bfloat162*)(cl + o0) = split_lo2(v0.x, v0.y, h0);
                *(__nv_bfloat162*)(cl + o1) = split_lo2(v1.x, v1.y, h1);
            }
        }
    }
    if (doAmax) {
        #pragma unroll
        for (int o = 16; o; o >>= 1)
            amax = fmaxf(amax, __shfl_xor_sync(~0u, amax, o));
        if (lane == 0) atomicMax(&g_amax[3], __float_as_uint(amax));
    }
}

// ---------------------------------------------------------------------------
// amax / scale kernels
// ---------------------------------------------------------------------------
__global__ void init_amax_kernel() {
    if (threadIdx.x < 4) g_amax[threadIdx.x] = 0u;
}
__global__ void amax_kernel(const float* __restrict__ p, long n4, int slot) {
    __shared__ float sh[256];
    float m = 0.f;
    for (long i = (long)blockIdx.x * 256 + threadIdx.x; i < n4; i += (long)gridDim.x * 256) {
        float4 v = ((const float4*)p)[i];
        m = fmaxf(m, fmaxf(fmaxf(fabsf(v.x), fabsf(v.y)), fmaxf(fabsf(v.z), fabsf(v.w))));
    }
    sh[threadIdx.x] = m;
    __syncthreads();
    for (int o = 128; o; o >>= 1) {
        if (threadIdx.x < o) sh[threadIdx.x] = fmaxf(sh[threadIdx.x], sh[threadIdx.x + o]);
        __syncthreads();
    }
    if (threadIdx.x == 0) atomicMax(&g_amax[slot], __float_as_uint(sh[0]));
}
__global__ void scales_ab_kernel() {
    if (threadIdx.x == 0) {
        g_scales[0] = (__uint_as_float(g_amax[0]) + 0.001f) / 32000.f;
        g_scales[1] = fmaxf(__uint_as_float(g_amax[1]), 1e-30f) / 32000.f;
        g_scales[2] = fmaxf(__uint_as_float(g_amax[2]), 1e-30f) / 32000.f;
    }
}
__global__ void scale_z_kernel() {
    if (threadIdx.x == 0)
        g_scales[3] = fmaxf(__uint_as_float(g_amax[3]), 1e-30f) / 32000.f;
}

// ---------------------------------------------------------------------------
// fp32 [R,C] -> s8 pair transposed [C,R]  (weights)
// ---------------------------------------------------------------------------
__global__ void tquant_kernel(const float* __restrict__ in, int ldin,
                              int8_t* __restrict__ o1, int8_t* __restrict__ o0,
                              int ldo, int slot)
{
    __shared__ float tile[32][33];
    const int r0 = blockIdx.y * 32, c0 = blockIdx.x * 32;
    const int tx = threadIdx.x, ty = threadIdx.y;
    #pragma unroll
    for (int i = 0; i < 4; i++)
        tile[ty + i * 8][tx] = in[(long)(r0 + ty + i * 8) * ldin + c0 + tx];
    __syncthreads();
    const float inv_s = 1.f / g_scales[slot];
    const int t  = ty * 32 + tx;
    const int rp = t & 15;
    const int cb = t >> 4;
    #pragma unroll
    for (int pass = 0; pass < 2; pass++) {
        const int cl_ = cb + pass * 16;
        int8_t a1, a0, b1, b0;
        quant16(tile[2 * rp][cl_],     inv_s, a1, a0);
        quant16(tile[2 * rp + 1][cl_], inv_s, b1, b0);
        const long o = (long)(c0 + cl_) * ldo + r0 + 2 * rp;
        *(char2*)(o1 + o) = make_char2(a1, b1);
        *(char2*)(o0 + o) = make_char2(a0, b0);
    }
}

// ---------------------------------------------------------------------------
// fp32 [R,C] -> bf16 hi/lo transposed [C,R] (V only, batched via strides)
// ---------------------------------------------------------------------------
__global__ void tsplit_kernel(const float* __restrict__ in, long sIo, long sIi, int ldin,
                              __nv_bfloat16* __restrict__ hi, __nv_bfloat16* __restrict__ lo,
                              long sOo, long sOi, int ldo, int inner)
{
    __shared__ float tile[32][33];
    const int z = blockIdx.z, zo = z / inner, zi = z - zo * inner;
    in += zo * sIo + zi * sIi;
    hi += zo * sOo + zi * sOi;
    lo += zo * sOo + zi * sOi;
    const int r0 = blockIdx.y * 32, c0 = blockIdx.x * 32;
    const int tx = threadIdx.x, ty = threadIdx.y;
    #pragma unroll
    for (int i = 0; i < 4; i++)
        tile[ty + i * 8][tx] = in[(long)(r0 + ty + i * 8) * ldin + c0 + tx];
    __syncthreads();
    const int t  = ty * 32 + tx;
    const int rp = t & 15;
    const int cb = t >> 4;
    #pragma unroll
    for (int pass = 0; pass < 2; pass++) {
        const int cl_ = cb + pass * 16;
        const float v0 = tile[2 * rp][cl_];
        const float v1 = tile[2 * rp + 1][cl_];
        __nv_bfloat162 h = split_hi2(v0, v1);
        const long o = (long)(c0 + cl_) * ldo + r0 + 2 * rp;
        *(__nv_bfloat162*)(hi + o) = h;
        *(__nv_bfloat162*)(lo + o) = split_lo2(v0, v1, h);
    }
}

// ---------------------------------------------------------------------------
// Z fp32 -> s8 pair (elementwise)
// ---------------------------------------------------------------------------
__global__ void zquant_kernel(const float* __restrict__ Z,
                              int8_t* __restrict__ Z1, int8_t* __restrict__ Z0, long n)
{
    long i = ((long)blockIdx.x * blockDim.x + threadIdx.x) * 4;
    if (i >= n) return;
    const float inv_s = 1.f / g_scales[3];
    float4 v = *(const float4*)(Z + i);
    int8_t h0, l0, h1, l1, h2, l2, h3, l3;
    quant16(v.x, inv_s, h0, l0);
    quant16(v.y, inv_s, h1, l1);
    quant16(v.z, inv_s, h2, l2);
    quant16(v.w, inv_s, h3, l3);
    *(char4*)(Z1 + i) = make_char4(h0, h1, h2, h3);
    *(char4*)(Z0 + i) = make_char4(l0, l1, l2, l3);
}

// ---------------------------------------------------------------------------
// build X (gather + transpose + PE), writes fp32 AND s8 pair
// ---------------------------------------------------------------------------
__global__ void build_x_kernel(const float* __restrict__ ref,
                               const float* __restrict__ hd,
                               float* __restrict__ X,
                               int8_t* __restrict__ X1,
                               int8_t* __restrict__ X0)
{
    __shared__ float tile[32][33];
    const int b  = blockIdx.z;
    const int f0 = blockIdx.x * 32;
    const int t0 = blockIdx.y * 32;
    const int tx = threadIdx.x, ty = threadIdx.y;

#pragma unroll
    for (int i = 0; i < 4; i++) {
        int f  = f0 + ty + i * 8;
        int n_ = f >> 10;
        int s  = f & 1023;
        int hh = s >> 5;
        int ww = s & 31;
        const float* src = (ww < 16)
            ? ref + ((long)(((b * 8 + n_) * 32 + hh) * 16 + ww)) * 1024
            : hd  + ((long)(((b * 8 + n_) * 32 + hh) * 16 + (ww - 16))) * 1024;
        tile[ty + i * 8][tx] = src[t0 + tx];
    }
    __syncthreads();
    const float inv_s = 1.f / g_scales[0];
#pragma unroll
    for (int i = 0; i < 4; i++) {
        int t = t0 + ty + i * 8;
        int f = f0 + tx;
        float freq = __expf((float)f * (-9.210340371976184f / 4096.0f));
        float ang  = (float)t * freq;
        float pe   = (f & 1) ? cosf(ang) : sinf(ang);
        float v    = tile[tx][ty + i * 8] + 0.001f * pe;
        long  o    = (long)b * PLANE + (long)t * DEMB + f;
        X[o] = v;
        int8_t q1, q0;
        quant16(v, inv_s, q1, q0);
        X1[o] = q1;
        X0[o] = q0;
    }
}

// ---------------------------------------------------------------------------
// Softmax over rows of S, writing bf16 hi/lo P directly.
// ---------------------------------------------------------------------------
__global__ void softmax_kernel(const float* __restrict__ S,
                               __nv_bfloat16* __restrict__ Ph,
                               __nv_bfloat16* __restrict__ Pl)
{
    __shared__ float red[8];
    const int tid  = threadIdx.x;
    const int lane = tid & 31, warp = tid >> 5;
    const float4* row = (const float4*)(S + (long)blockIdx.x * SEQ);
    float4 v = row[tid];

    float m = fmaxf(fmaxf(v.x, v.y), fmaxf(v.z, v.w));
#pragma unroll
    for (int o = 16; o; o >>= 1) m = fmaxf(m, __shfl_xor_sync(~0u, m, o));
    if (lane == 0) red[warp] = m;
    __syncthreads();
    float M = red[0];
#pragma unroll
    for (int i = 1; i < 8; i++) M = fmaxf(M, red[i]);

    v.x = __expf(v.x - M); v.y = __expf(v.y - M);
    v.z = __expf(v.z - M); v.w = __expf(v.w - M);
    float s = v.x + v.y + v.z + v.w;
#pragma unroll
    for (int o = 16; o; o >>= 1) s += __shfl_xor_sync(~0u, s, o);
    __syncthreads();
    if (lane == 0) red[warp] = s;
    __syncthreads();
    float T = 0.f;
#pragma unroll
    for (int i = 0; i < 8; i++) T += red[i];
    float inv = 1.0f / T;
    v.x *= inv; v.y *= inv; v.z *= inv; v.w *= inv;

    const long o = (long)blockIdx.x * SEQ + tid * 4;
    __nv_bfloat162 h0 = split_hi2(v.x, v.y);
    __nv_bfloat162 h1 = split_hi2(v.z, v.w);
    *(__nv_bfloat162*)(Ph + o)     = h0;
    *(__nv_bfloat162*)(Ph + o + 2) = h1;
    *(__nv_bfloat162*)(Pl + o)     = split_lo2(v.x, v.y, h0);
    *(__nv_bfloat162*)(Pl + o + 2) = split_lo2(v.z, v.w, h1);
}

// ---------------------------------------------------------------------------
// LayerNorm statistics + output
// ---------------------------------------------------------------------------
__global__ void reduce_partial_kernel(const float* __restrict__ O,
                                      double* __restrict__ part)
{
    __shared__ double sh[256], sh2[256];
    const int b   = blockIdx.y;
    const int tid = threadIdx.x;
    const float* p = O + (long)b * PLANE;
    const int base = blockIdx.x * 256 + tid;
    double s = 0.0, s2 = 0.0;
#pragma unroll
    for (int i = 0; i < 32; i++) {
        float v = p[base + i * 262144];
        s  += v;
        s2 += (double)v * v;
    }
    sh[tid] = s; sh2[tid] = s2;
    __syncthreads();
    for (int o = 128; o; o >>= 1) {
        if (tid < o) { sh[tid] += sh[tid + o]; sh2[tid] += sh2[tid + o]; }
        __syncthreads();
    }
    if (tid == 0) {
        part[(b * 1024 + blockIdx.x) * 2 + 0] = sh[0];
        part[(b * 1024 + blockIdx.x) * 2 + 1] = sh2[0];
    }
}

__global__ void finalize_stats_kernel(const double* __restrict__ part)
{
    __shared__ double sh[256], sh2[256];
    const int b = blockIdx.x, tid = threadIdx.x;
    double s = 0.0, s2 = 0.0;
    for (int i = tid; i < 1024; i += 256) {
        s  += part[(b * 1024 + i) * 2 + 0];
        s2 += part[(b * 1024 + i) * 2 + 1];
    }
    sh[tid] = s; sh2[tid] = s2;
    __syncthreads();
    for (int o = 128; o; o >>= 1) {
        if (tid < o) { sh[tid] += sh[tid + o]; sh2[tid] += sh2[tid + o]; }
        __syncthreads();
    }
    if (tid == 0) {
        double n    = (double)PLANE;
        double mean = sh[0] / n;
        double var  = sh2[0] / n - mean * mean;
        g_mean[b] = mean;
        g_rstd[b] = rsqrt(var + 1e-6);
    }
}

__global__ void ln_out_kernel(const float* __restrict__ O,
                              const float* __restrict__ gamma,
                              const float* __restrict__ beta,
                              float* __restrict__ out)
{
    __shared__ float tile[32][33];
    const int bz = blockIdx.z;
    const int b  = bz >> 3;
    const int nf = (bz & 7) * 1024;
    const int c0 = blockIdx.x * 32;
    const int t0 = blockIdx.y * 32;
    const int tx = threadIdx.x, ty = threadIdx.y;
    const float mean = (float)g_mean[b];
    const float rstd = (float)g_rstd[b];

#pragma unroll
    for (int i = 0; i < 4; i++) {
        int t   = t0 + ty + i * 8;
        long fi = (long)t * DEMB + nf + c0 + tx;
        float v = O[(long)b * PLANE + fi];
        tile[ty + i * 8][tx] = (v - mean) * rstd * gamma[fi] + beta[fi];
    }
    __syncthreads();
#pragma unroll
    for (int i = 0; i < 4; i++) {
        int c = c0 + ty + i * 8;
        out[((long)bz * 1024 + c) * 1024 + t0 + tx] = tile[tx][ty + i * 8];
    }
}

// ---------------------------------------------------------------------------
// Launcher
// ---------------------------------------------------------------------------
extern "C" void kernel_launch(void* const* d_in, const int* in_sizes, int n_in,
                              void* d_out, int out_size)
{
    const float* ref_img = (const float*)d_in[0];
    const float* hdmap   = (const float*)d_in[1];
    const float* w_q     = (const float*)d_in[2];
    const float* w_k     = (const float*)d_in[3];
    const float* w_v     = (const float*)d_in[4];
    const float* w_o     = (const float*)d_in[5];
    const float* gamma   = (const float*)d_in[6];
    const float* beta    = (const float*)d_in[7];
    float* out = (float*)d_out;

    float *X, *V, *S, *Z, *O;  double* part;
    int8_t *X1, *X0, *W1, *W0, *Wo1, *Wo0, *Z1, *Z0;
    __nv_bfloat16 *Qh, *Ql, *Kh, *Kl, *Vth, *Vtl, *Ph, *Pl;
    cudaGetSymbolAddress((void**)&X, g_X);     cudaGetSymbolAddress((void**)&V, g_V);
    cudaGetSymbolAddress((void**)&S, g_S);     cudaGetSymbolAddress((void**)&Z, g_Z);
    cudaGetSymbolAddress((void**)&O, g_O);     cudaGetSymbolAddress((void**)&part, g_part);
    cudaGetSymbolAddress((void**)&X1, g_X1);   cudaGetSymbolAddress((void**)&X0, g_X0);
    cudaGetSymbolAddress((void**)&W1, g_W1);   cudaGetSymbolAddress((void**)&W0, g_W0);
    cudaGetSymbolAddress((void**)&Wo1, g_Wo1); cudaGetSymbolAddress((void**)&Wo0, g_Wo0);
    cudaGetSymbolAddress((void**)&Z1, g_Z1);   cudaGetSymbolAddress((void**)&Z0, g_Z0);
    cudaGetSymbolAddress((void**)&Qh, g_Qh);   cudaGetSymbolAddress((void**)&Ql, g_Ql);
    cudaGetSymbolAddress((void**)&Kh, g_Kh);   cudaGetSymbolAddress((void**)&Kl, g_Kl);
    cudaGetSymbolAddress((void**)&Vth, g_Vth); cudaGetSymbolAddress((void**)&Vtl, g_Vtl);
    cudaGetSymbolAddress((void**)&Ph, g_Ph);   cudaGetSymbolAddress((void**)&Pl, g_Pl);

    cudaFuncSetAttribute(mma_gemm,  cudaFuncAttributeMaxDynamicSharedMemorySize, SMEM_DYN);
    cudaFuncSetAttribute(imma_gemm, cudaFuncAttributeMaxDynamicSharedMemorySize, ISMEM);

    const dim3 tb32x8(32, 8);
    const long NIN = (long)BATCH * NHEAD * 32 * 16 * 1024;       // 16.78M
    const long NW  = (long)DEMB * QKVDIM;                        // 16.78M

    // 0) scales: amax reductions (deterministic atomicMax on uint bits)
    init_amax_kernel<<<1, 32>>>();
    amax_kernel<<<512, 256>>>(ref_img, NIN / 4, 0);
    amax_kernel<<<512, 256>>>(hdmap,   NIN / 4, 0);
    amax_kernel<<<512, 256>>>(w_q, NW / 4, 1);
    amax_kernel<<<512, 256>>>(w_k, NW / 4, 1);
    amax_kernel<<<512, 256>>>(w_v, NW / 4, 1);
    amax_kernel<<<512, 256>>>(w_o, NW / 4, 2);
    scales_ab_kernel<<<1, 32>>>();

    // 1) build X (fp32 + s8 pair)
    build_x_kernel<<<dim3(DEMB / 32, SEQ / 32, BATCH), tb32x8>>>(ref_img, hdmap, X, X1, X0);

    // 2) weight transpose + quantize: Wqkv [6144,8192] s8 pair; Wo [8192,2048]
    tquant_kernel<<<dim3(QKVDIM / 32, DEMB / 32), tb32x8>>>(w_q, QKVDIM, W1, W0, DEMB, 1);
    tquant_kernel<<<dim3(QKVDIM / 32, DEMB / 32), tb32x8>>>(
        w_k, QKVDIM, W1 + (long)QKVDIM * DEMB, W0 + (long)QKVDIM * DEMB, DEMB, 1);
    tquant_kernel<<<dim3(QKVDIM / 32, DEMB / 32), tb32x8>>>(
        w_v, QKVDIM, W1 + (long)2 * QKVDIM * DEMB, W0 + (long)2 * QKVDIM * DEMB, DEMB, 1);
    tquant_kernel<<<dim3(DEMB / 32, QKVDIM / 32), tb32x8>>>(w_o, DEMB, Wo1, Wo0, QKVDIM, 2);

    // 3) fused QKV projection on IMMA: [4096,8192] x [8192,6144]
    imma_gemm<<<dim3(3 * QKVDIM / 128, TOK_TOTAL / 128), 256, ISMEM>>>(
        X1, X0, DEMB, W1, W0, DEMB,
        V, Qh, Ql, Kh, Kl, QKVDIM, nullptr, 0, 1, DEMB, 1);

    // 4) transpose+split V per head -> Vt[b,h,d,t] bf16
    tsplit_kernel<<<dim3(DKV / 32, SEQ / 32, BATCH * NHEAD), tb32x8>>>(
        V, (long)SEQ * QKVDIM, DKV, QKVDIM,
        Vth, Vtl, (long)NHEAD * DKV * SEQ, (long)DKV * SEQ, SEQ, NHEAD);

    // 5) scores S = (1/16) Q K^T per (b,h) on bf16 HMMA
    const long sQKo = (long)SEQ * QKVDIM;
    const long sSo  = (long)NHEAD * SEQ * SEQ;
    mma_gemm<<<dim3(SEQ / 128, SEQ / 128, BATCH * NHEAD), 256, SMEM_DYN>>>(
        Qh, Ql, QKVDIM, sQKo, DKV,
        Kh, Kl, QKVDIM, sQKo, DKV,
        S, nullptr, nullptr, SEQ, sSo, (long)SEQ * SEQ,
        0, DKV, NHEAD, 0.0625f);

    // 6) softmax with fused P split
    softmax_kernel<<<BATCH * NHEAD * SEQ, 256>>>(S, Ph, Pl);

    // 7) Z = P @ V per (b,h) on bf16 HMMA -> Z fp32 + amax
    mma_gemm<<<dim3(DKV / 128, SEQ / 128, BATCH * NHEAD), 256, SMEM_DYN>>>(
        Ph, Pl, SEQ, sSo, (long)SEQ * SEQ,
        Vth, Vtl, SEQ, (long)NHEAD * DKV * SEQ, (long)DKV * SEQ,
        Z, nullptr, nullptr, QKVDIM, sQKo, DKV,
        1, SEQ, NHEAD, 1.0f);

    // 8) Z quantize, then O = Z @ w_o + X on IMMA
    scale_z_kernel<<<1, 32>>>();
    {
        long n = (long)BATCH * SEQ * QKVDIM;
        zquant_kernel<<<(unsigned)(n / 4 / 256), 256>>>(Z, Z1, Z0, n);
    }
    imma_gemm<<<dim3(DEMB / 128, TOK_TOTAL / 128), 256, ISMEM>>>(
        Z1, Z0, QKVDIM, Wo1, Wo0, QKVDIM,
        O, nullptr, nullptr, nullptr, nullptr, DEMB, X, 3, 2, QKVDIM, 0);

    // 9) LayerNorm stats + normalize/transpose out
    reduce_partial_kernel<<<dim3(1024, BATCH), 256>>>(O, part);
    finalize_stats_kernel<<<BATCH, 256>>>(part);
    ln_out_kernel<<<dim3(32, 32, BATCH * NHEAD), tb32x8>>>(O, gamma, beta, out);
}

// round 11
// speedup vs baseline: 2.7004x; 2.7004x over previous
#include <cuda_runtime.h>
#include <cuda_bf16.h>
#include <cstdint>
#include <math.h>

// ---------------------------------------------------------------------------
// Problem constants
// ---------------------------------------------------------------------------
#define BATCH      4
#define SEQ        1024
#define DEMB       8192
#define NHEAD      8
#define DKV        256
#define QKVDIM     (NHEAD * DKV)          // 2048
#define TOK_TOTAL  (BATCH * SEQ)          // 4096
#define PLANE      ((long)SEQ * DEMB)

// ---------------------------------------------------------------------------
// Scratch (static device allocations — no cudaMalloc allowed)
// ---------------------------------------------------------------------------
__device__ __align__(256) float  g_X[(long)BATCH * SEQ * DEMB];
__device__ __align__(256) float  g_V[(long)BATCH * SEQ * QKVDIM];
__device__ __align__(256) float  g_S[(long)BATCH * NHEAD * SEQ * SEQ];
__device__ __align__(256) float  g_O[(long)BATCH * SEQ * DEMB];
__device__ double g_part[BATCH * 1024 * 2];
__device__ double g_mean[BATCH];
__device__ double g_rstd[BATCH];

__device__ __align__(256) __nv_bfloat16 g_Xh[(long)BATCH * SEQ * DEMB];
__device__ __align__(256) __nv_bfloat16 g_Xl[(long)BATCH * SEQ * DEMB];
__device__ __align__(256) __nv_bfloat16 g_Wqkvth[(long)3 * QKVDIM * DEMB];
__device__ __align__(256) __nv_bfloat16 g_Wqkvtl[(long)3 * QKVDIM * DEMB];
__device__ __align__(256) __nv_bfloat16 g_Woth[(long)DEMB * QKVDIM];
__device__ __align__(256) __nv_bfloat16 g_Wotl[(long)DEMB * QKVDIM];
__device__ __align__(256) __nv_bfloat16 g_Qh[(long)BATCH * SEQ * QKVDIM];
__device__ __align__(256) __nv_bfloat16 g_Ql[(long)BATCH * SEQ * QKVDIM];
__device__ __align__(256) __nv_bfloat16 g_Kh[(long)BATCH * SEQ * QKVDIM];
__device__ __align__(256) __nv_bfloat16 g_Kl[(long)BATCH * SEQ * QKVDIM];
__device__ __align__(256) __nv_bfloat16 g_Vth[(long)BATCH * NHEAD * DKV * SEQ];
__device__ __align__(256) __nv_bfloat16 g_Vtl[(long)BATCH * NHEAD * DKV * SEQ];
__device__ __align__(256) __nv_bfloat16 g_Ph[(long)BATCH * NHEAD * SEQ * SEQ];
__device__ __align__(256) __nv_bfloat16 g_Pl[(long)BATCH * NHEAD * SEQ * SEQ];
__device__ __align__(256) __nv_bfloat16 g_Zh[(long)BATCH * SEQ * QKVDIM];
__device__ __align__(256) __nv_bfloat16 g_Zl[(long)BATCH * SEQ * QKVDIM];

// ---------------------------------------------------------------------------
// PTX helpers (sm_80-compatible: cp.async, ldmatrix, mma.sync)
// ---------------------------------------------------------------------------
__device__ __forceinline__ uint32_t smem_u32(const void* p) {
    uint32_t a;
    asm("{ .reg .u64 t; cvta.to.shared.u64 t, %1; cvt.u32.u64 %0, t; }"
        : "=r"(a) : "l"(p));
    return a;
}
__device__ __forceinline__ void cpasync16(uint32_t dst, const void* src) {
    asm volatile("cp.async.cg.shared.global [%0], [%1], 16;" :: "r"(dst), "l"(src));
}
__device__ __forceinline__ void cp_commit() {
    asm volatile("cp.async.commit_group;" ::: "memory");
}
template <int N> __device__ __forceinline__ void cp_wait() {
    asm volatile("cp.async.wait_group %0;" :: "n"(N) : "memory");
}
__device__ __forceinline__ void ldsm4(uint32_t* r, uint32_t addr) {
    asm volatile("ldmatrix.sync.aligned.m8n8.x4.shared.b16 {%0,%1,%2,%3}, [%4];"
                 : "=r"(r[0]), "=r"(r[1]), "=r"(r[2]), "=r"(r[3]) : "r"(addr));
}
__device__ __forceinline__ void ldsm2(uint32_t* r, uint32_t addr) {
    asm volatile("ldmatrix.sync.aligned.m8n8.x2.shared.b16 {%0,%1}, [%2];"
                 : "=r"(r[0]), "=r"(r[1]) : "r"(addr));
}
__device__ __forceinline__ void mma16816(float* c, const uint32_t* a, const uint32_t* b) {
    asm volatile(
        "mma.sync.aligned.m16n8k16.row.col.f32.bf16.bf16.f32 "
        "{%0,%1,%2,%3}, {%4,%5,%6,%7}, {%8,%9}, {%0,%1,%2,%3};"
        : "+f"(c[0]), "+f"(c[1]), "+f"(c[2]), "+f"(c[3])
        : "r"(a[0]), "r"(a[1]), "r"(a[2]), "r"(a[3]), "r"(b[0]), "r"(b[1]));
}
__device__ __forceinline__ __nv_bfloat162 split_hi2(float x, float y) {
    __nv_bfloat162 h;
    h.x = __float2bfloat16(x); h.y = __float2bfloat16(y);
    return h;
}
__device__ __forceinline__ __nv_bfloat162 split_lo2(float x, float y, __nv_bfloat162 h) {
    __nv_bfloat162 l;
    l.x = __float2bfloat16(x - __bfloat162float(h.x));
    l.y = __float2bfloat16(y - __bfloat162float(h.y));
    return l;
}

// ---------------------------------------------------------------------------
// Split-precision bf16 GEMM on mma.sync (round-7 proven config).
// acc = alpha * (Ah*Bh^T + Ah*Bl^T + Al*Bh^T) (+ D), fp32 accum in regs.
// Tile 128x128, K-chunk 64, 3-stage cp.async pipeline, XOR-swizzled smem.
// mode 0: outputs Cf (fp32) and/or Ch/Cl (bf16 hi/lo).
// mode 1 (fused QKV): column segment seg=col0>>11 routes to
//         seg0 -> Ch/Cl (Q), seg1 -> C2h/C2l (K), seg2 -> Cf (V fp32); ldc=2048.
// Batch z: offset = (z/inner)*so + (z%inner)*si per operand.
// ---------------------------------------------------------------------------
#define KC      64
#define TILE_B  16384                     // 128 rows x 128 bytes
#define STG_B   (4 * TILE_B)              // Ah, Al, Bh, Bl per stage
#define NSTAGE  3
#define SMEM_DYN (NSTAGE * STG_B)         // 196608

__global__ __launch_bounds__(256, 1)
void mma_gemm(const __nv_bfloat16* __restrict__ Ah, const __nv_bfloat16* __restrict__ Al,
              int lda, long sAo, long sAi,
              const __nv_bfloat16* __restrict__ Bh, const __nv_bfloat16* __restrict__ Bl,
              int ldb, long sBo, long sBi,
              float* __restrict__ Cf,
              __nv_bfloat16* __restrict__ Ch, __nv_bfloat16* __restrict__ Cl,
              __nv_bfloat16* __restrict__ C2h, __nv_bfloat16* __restrict__ C2l,
              int ldc, long sCo, long sCi,
              const float* __restrict__ D,
              int K, int inner, float alpha, int mode)
{
    extern __shared__ __align__(128) char dsm_raw[];
    const uint32_t dsm0 = smem_u32(dsm_raw);

    const int tid  = threadIdx.x;
    const int lane = tid & 31;
    const int wid  = tid >> 5;
    const int wm   = wid & 1;             // warp row (2)
    const int wn   = wid >> 1;            // warp col (4)

    const int z  = blockIdx.z;
    const int zo = z / inner, zi = z - zo * inner;
    Ah += zo * sAo + zi * sAi;  Al += zo * sAo + zi * sAi;
    Bh += zo * sBo + zi * sBi;  Bl += zo * sBo + zi * sBi;
    const long coff = zo * sCo + zi * sCi;

    // grouped rasterization: GROUP M-tiles per stripe, sweep N within stripe
    int pid_m, pid_n;
    {
        const int ntm = gridDim.y, ntn = gridDim.x;
        const int lin = blockIdx.y * ntn + blockIdx.x;
        const int G = 8;
        const int width = G * ntn;
        const int grp = lin / width;
        const int rem = lin - grp * width;
        const int m0  = grp * G;
        const int gsz = (ntm - m0 < G) ? (ntm - m0) : G;
        pid_m = m0 + rem % gsz;
        pid_n = rem / gsz;
    }
    const int row0 = pid_m * 128;
    const int col0 = pid_n * 128;

    // cp.async geometry: 1024 16B-chunks per tile; 4 per thread per tile
    int rr[4], cc[4]; uint32_t swo[4];
    #pragma unroll
    for (int j = 0; j < 4; j++) {
        int idx = tid + j * 256;
        rr[j] = idx >> 3;
        cc[j] = idx & 7;
        swo[j] = (uint32_t)(rr[j] * 128 + ((cc[j] ^ (rr[j] & 7)) << 4));
    }
    const __nv_bfloat16* tp[4] = {Ah, Al, Bh, Bl};
    const int nk = K / KC;

    auto load_stage = [&](int s, int k0) {
        const uint32_t sb = dsm0 + s * STG_B;
        #pragma unroll
        for (int t = 0; t < 4; t++) {
            const __nv_bfloat16* g = tp[t];
            const long ld = (t < 2) ? lda : ldb;
            const int  rb = (t < 2) ? row0 : col0;
            const uint32_t tb = sb + t * TILE_B;
            #pragma unroll
            for (int j = 0; j < 4; j++)
                cpasync16(tb + swo[j], g + (long)(rb + rr[j]) * ld + k0 + cc[j] * 8);
        }
        cp_commit();
    };

    // ldmatrix lane geometry
    const int l7   = lane & 7;
    const int aRow = wm * 64 + l7 + ((lane >> 3) & 1) * 8;
    const int aSel = (lane >> 4) & 1;
    const int bRow = wn * 32 + l7;
    const int bSel = (lane >> 3) & 1;
    const uint32_t aRowOff = (uint32_t)aRow * 128;
    const uint32_t bRowOff = (uint32_t)bRow * 128;

    float acc[4][4][4];
    #pragma unroll
    for (int mt = 0; mt < 4; mt++)
        #pragma unroll
        for (int nt = 0; nt < 4; nt++)
            #pragma unroll
            for (int q = 0; q < 4; q++) acc[mt][nt][q] = 0.f;

    load_stage(0, 0);
    load_stage(1, KC);

    for (int i = 0; i < nk; ++i) {
        const int s = i % NSTAGE;
        if (i + 1 < nk) cp_wait<1>(); else cp_wait<0>();
        __syncthreads();
        if (i + 2 < nk) load_stage((i + 2) % NSTAGE, (i + 2) * KC);

        const uint32_t sb = dsm0 + s * STG_B;
        #pragma unroll
        for (int ks = 0; ks < 4; ++ks) {
            uint32_t ah[4][4], al[4][4], bh[4][2], bl[4][2];
            const uint32_t asw = (uint32_t)(((2 * ks + aSel) ^ l7) << 4);
            const uint32_t bsw = (uint32_t)(((2 * ks + bSel) ^ l7) << 4);
            #pragma unroll
            for (int mt = 0; mt < 4; mt++) {
                uint32_t ad = sb + aRowOff + mt * 2048 + asw;
                ldsm4(ah[mt], ad);
                ldsm4(al[mt], ad + TILE_B);
            }
            #pragma unroll
            for (int nt = 0; nt < 4; nt++) {
                uint32_t bd = sb + 2 * TILE_B + bRowOff + nt * 1024 + bsw;
                ldsm2(bh[nt], bd);
                ldsm2(bl[nt], bd + TILE_B);
            }
            #pragma unroll
            for (int mt = 0; mt < 4; mt++)
                #pragma unroll
                for (int nt = 0; nt < 4; nt++) {
                    mma16816(acc[mt][nt], ah[mt], bh[nt]);
                    mma16816(acc[mt][nt], ah[mt], bl[nt]);
                    mma16816(acc[mt][nt], al[mt], bh[nt]);
                }
        }
        __syncthreads();
    }

    // ---- epilogue: mode-based routing
    float* cf = Cf;
    __nv_bfloat16 *ch = Ch, *cl = Cl;
    int cbase = col0;
    if (mode) {
        const int seg = col0 >> 11;
        cbase = col0 & 2047;
        if (seg == 0)      { cf = nullptr; ch = Ch;  cl = Cl;  }
        else if (seg == 1) { cf = nullptr; ch = C2h; cl = C2l; }
        else               { ch = nullptr; cl = nullptr; }
    }
    if (cf) cf += coff;
    if (ch) { ch += coff; cl += coff; }
    const float* dp = D ? (D + coff) : (const float*)0;

    const int cg = lane >> 2, tg = lane & 3;
    #pragma unroll
    for (int mt = 0; mt < 4; mt++) {
        #pragma unroll
        for (int nt = 0; nt < 4; nt++) {
            const int r = row0 + wm * 64 + mt * 16 + cg;
            const int c = cbase + wn * 32 + nt * 8 + tg * 2;
            const long o0 = (long)r * ldc + c;
            const long o1 = (long)(r + 8) * ldc + c;
            float2 v0, v1;
            v0.x = acc[mt][nt][0] * alpha; v0.y = acc[mt][nt][1] * alpha;
            v1.x = acc[mt][nt][2] * alpha; v1.y = acc[mt][nt][3] * alpha;
            if (dp) {
                float2 d0 = *(const float2*)(dp + o0);
                float2 d1 = *(const float2*)(dp + o1);
                v0.x += d0.x; v0.y += d0.y; v1.x += d1.x; v1.y += d1.y;
            }
            if (cf) {
                *(float2*)(cf + o0) = v0;
                *(float2*)(cf + o1) = v1;
            }
            if (ch) {
                __nv_bfloat162 h0 = split_hi2(v0.x, v0.y);
                __nv_bfloat162 h1 = split_hi2(v1.x, v1.y);
                *(__nv_bfloat162*)(ch + o0) = h0;
                *(__nv_bfloat162*)(ch + o1) = h1;
                *(__nv_bfloat162*)(cl + o0) = split_lo2(v0.x, v0.y, h0);
                *(__nv_bfloat162*)(cl + o1) = split_lo2(v1.x, v1.y, h1);
            }
        }
    }
}

// ---------------------------------------------------------------------------
// fp32 [R,C] -> bf16 hi/lo transposed [C,R]  (batched via strides)
// ---------------------------------------------------------------------------
__global__ void tsplit_kernel(const float* __restrict__ in, long sIo, long sIi, int ldin,
                              __nv_bfloat16* __restrict__ hi, __nv_bfloat16* __restrict__ lo,
                              long sOo, long sOi, int ldo, int inner)
{
    __shared__ float tile[32][33];
    const int z = blockIdx.z, zo = z / inner, zi = z - zo * inner;
    in += zo * sIo + zi * sIi;
    hi += zo * sOo + zi * sOi;
    lo += zo * sOo + zi * sOi;
    const int r0 = blockIdx.y * 32, c0 = blockIdx.x * 32;
    const int tx = threadIdx.x, ty = threadIdx.y;
    #pragma unroll
    for (int i = 0; i < 4; i++)
        tile[ty + i * 8][tx] = in[(long)(r0 + ty + i * 8) * ldin + c0 + tx];
    __syncthreads();
    const int t  = ty * 32 + tx;
    const int rp = t & 15;
    const int cb = t >> 4;
    #pragma unroll
    for (int pass = 0; pass < 2; pass++) {
        const int cl_ = cb + pass * 16;
        const float v0 = tile[2 * rp][cl_];
        const float v1 = tile[2 * rp + 1][cl_];
        __nv_bfloat162 h = split_hi2(v0, v1);
        const long o = (long)(c0 + cl_) * ldo + r0 + 2 * rp;
        *(__nv_bfloat162*)(hi + o) = h;
        *(__nv_bfloat162*)(lo + o) = split_lo2(v0, v1, h);
    }
}

// ---------------------------------------------------------------------------
// build X (gather + transpose + PE) writing fp32 AND bf16 hi/lo
// ---------------------------------------------------------------------------
__global__ void build_x_kernel(const float* __restrict__ ref,
                               const float* __restrict__ hd,
                               float* __restrict__ X,
                               __nv_bfloat16* __restrict__ Xh,
                               __nv_bfloat16* __restrict__ Xl)
{
    __shared__ float tile[32][33];
    const int b  = blockIdx.z;
    const int f0 = blockIdx.x * 32;
    const int t0 = blockIdx.y * 32;
    const int tx = threadIdx.x, ty = threadIdx.y;

#pragma unroll
    for (int i = 0; i < 4; i++) {
        int f  = f0 + ty + i * 8;
        int n_ = f >> 10;
        int s  = f & 1023;
        int hh = s >> 5;
        int ww = s & 31;
        const float* src = (ww < 16)
            ? ref + ((long)(((b * 8 + n_) * 32 + hh) * 16 + ww)) * 1024
            : hd  + ((long)(((b * 8 + n_) * 32 + hh) * 16 + (ww - 16))) * 1024;
        tile[ty + i * 8][tx] = src[t0 + tx];
    }
    __syncthreads();
#pragma unroll
    for (int i = 0; i < 4; i++) {
        int t = t0 + ty + i * 8;
        int f = f0 + tx;
        float freq = __expf((float)f * (-9.210340371976184f / 4096.0f));
        float ang  = (float)t * freq;
        float pe   = (f & 1) ? cosf(ang) : sinf(ang);
        float v    = tile[tx][ty + i * 8] + 0.001f * pe;
        long  o    = (long)b * PLANE + (long)t * DEMB + f;
        X[o] = v;
        __nv_bfloat16 h = __float2bfloat16(v);
        Xh[o] = h;
        Xl[o] = __float2bfloat16(v - __bfloat162float(h));
    }
}

// ---------------------------------------------------------------------------
// Softmax over rows of S, writing bf16 hi/lo P directly.
// ---------------------------------------------------------------------------
__global__ void softmax_kernel(const float* __restrict__ S,
                               __nv_bfloat16* __restrict__ Ph,
                               __nv_bfloat16* __restrict__ Pl)
{
    __shared__ float red[8];
    const int tid  = threadIdx.x;
    const int lane = tid & 31, warp = tid >> 5;
    const float4* row = (const float4*)(S + (long)blockIdx.x * SEQ);
    float4 v = row[tid];

    float m = fmaxf(fmaxf(v.x, v.y), fmaxf(v.z, v.w));
#pragma unroll
    for (int o = 16; o; o >>= 1) m = fmaxf(m, __shfl_xor_sync(~0u, m, o));
    if (lane == 0) red[warp] = m;
    __syncthreads();
    float M = red[0];
#pragma unroll
    for (int i = 1; i < 8; i++) M = fmaxf(M, red[i]);

    v.x = __expf(v.x - M); v.y = __expf(v.y - M);
    v.z = __expf(v.z - M); v.w = __expf(v.w - M);
    float s = v.x + v.y + v.z + v.w;
#pragma unroll
    for (int o = 16; o; o >>= 1) s += __shfl_xor_sync(~0u, s, o);
    __syncthreads();
    if (lane == 0) red[warp] = s;
    __syncthreads();
    float T = 0.f;
#pragma unroll
    for (int i = 0; i < 8; i++) T += red[i];
    float inv = 1.0f / T;
    v.x *= inv; v.y *= inv; v.z *= inv; v.w *= inv;

    const long o = (long)blockIdx.x * SEQ + tid * 4;
    __nv_bfloat162 h0 = split_hi2(v.x, v.y);
    __nv_bfloat162 h1 = split_hi2(v.z, v.w);
    *(__nv_bfloat162*)(Ph + o)     = h0;
    *(__nv_bfloat162*)(Ph + o + 2) = h1;
    *(__nv_bfloat162*)(Pl + o)     = split_lo2(v.x, v.y, h0);
    *(__nv_bfloat162*)(Pl + o + 2) = split_lo2(v.z, v.w, h1);
}

// ---------------------------------------------------------------------------
// LayerNorm statistics + output
// ---------------------------------------------------------------------------
__global__ void reduce_partial_kernel(const float* __restrict__ O,
                                      double* __restrict__ part)
{
    __shared__ double sh[256], sh2[256];
    const int b   = blockIdx.y;
    const int tid = threadIdx.x;
    const float* p = O + (long)b * PLANE;
    const int base = blockIdx.x * 256 + tid;
    double s = 0.0, s2 = 0.0;
#pragma unroll
    for (int i = 0; i < 32; i++) {
        float v = p[base + i * 262144];
        s  += v;
        s2 += (double)v * v;
    }
    sh[tid] = s; sh2[tid] = s2;
    __syncthreads();
    for (int o = 128; o; o >>= 1) {
        if (tid < o) { sh[tid] += sh[tid + o]; sh2[tid] += sh2[tid + o]; }
        __syncthreads();
    }
    if (tid == 0) {
        part[(b * 1024 + blockIdx.x) * 2 + 0] = sh[0];
        part[(b * 1024 + blockIdx.x) * 2 + 1] = sh2[0];
    }
}

__global__ void finalize_stats_kernel(const double* __restrict__ part)
{
    __shared__ double sh[256], sh2[256];
    const int b = blockIdx.x, tid = threadIdx.x;
    double s = 0.0, s2 = 0.0;
    for (int i = tid; i < 1024; i += 256) {
        s  += part[(b * 1024 + i) * 2 + 0];
        s2 += part[(b * 1024 + i) * 2 + 1];
    }
    sh[tid] = s; sh2[tid] = s2;
    __syncthreads();
    for (int o = 128; o; o >>= 1) {
        if (tid < o) { sh[tid] += sh[tid + o]; sh2[tid] += sh2[tid + o]; }
        __syncthreads();
    }
    if (tid == 0) {
        double n    = (double)PLANE;
        double mean = sh[0] / n;
        double var  = sh2[0] / n - mean * mean;
        g_mean[b] = mean;
        g_rstd[b] = rsqrt(var + 1e-6);
    }
}

__global__ void ln_out_kernel(const float* __restrict__ O,
                              const float* __restrict__ gamma,
                              const float* __restrict__ beta,
                              float* __restrict__ out)
{
    __shared__ float tile[32][33];
    const int bz = blockIdx.z;
    const int b  = bz >> 3;
    const int nf = (bz & 7) * 1024;
    const int c0 = blockIdx.x * 32;
    const int t0 = blockIdx.y * 32;
    const int tx = threadIdx.x, ty = threadIdx.y;
    const float mean = (float)g_mean[b];
    const float rstd = (float)g_rstd[b];

#pragma unroll
    for (int i = 0; i < 4; i++) {
        int t   = t0 + ty + i * 8;
        long fi = (long)t * DEMB + nf + c0 + tx;
        float v = O[(long)b * PLANE + fi];
        tile[ty + i * 8][tx] = (v - mean) * rstd * gamma[fi] + beta[fi];
    }
    __syncthreads();
#pragma unroll
    for (int i = 0; i < 4; i++) {
        int c = c0 + ty + i * 8;
        out[((long)bz * 1024 + c) * 1024 + t0 + tx] = tile[tx][ty + i * 8];
    }
}

// ---------------------------------------------------------------------------
// Launcher
// ---------------------------------------------------------------------------
extern "C" void kernel_launch(void* const* d_in, const int* in_sizes, int n_in,
                              void* d_out, int out_size)
{
    const float* ref_img = (const float*)d_in[0];
    const float* hdmap   = (const float*)d_in[1];
    const float* w_q     = (const float*)d_in[2];
    const float* w_k     = (const float*)d_in[3];
    const float* w_v     = (const float*)d_in[4];
    const float* w_o     = (const float*)d_in[5];
    const float* gamma   = (const float*)d_in[6];
    const float* beta    = (const float*)d_in[7];
    float* out = (float*)d_out;

    float *X, *V, *S, *O;  double* part;
    __nv_bfloat16 *Xh, *Xl, *Wqkvth, *Wqkvtl, *Woth, *Wotl;
    __nv_bfloat16 *Qh, *Ql, *Kh, *Kl, *Vth, *Vtl, *Ph, *Pl, *Zh, *Zl;
    cudaGetSymbolAddress((void**)&X, g_X);     cudaGetSymbolAddress((void**)&V, g_V);
    cudaGetSymbolAddress((void**)&S, g_S);     cudaGetSymbolAddress((void**)&O, g_O);
    cudaGetSymbolAddress((void**)&part, g_part);
    cudaGetSymbolAddress((void**)&Xh, g_Xh);   cudaGetSymbolAddress((void**)&Xl, g_Xl);
    cudaGetSymbolAddress((void**)&Wqkvth, g_Wqkvth);
    cudaGetSymbolAddress((void**)&Wqkvtl, g_Wqkvtl);
    cudaGetSymbolAddress((void**)&Woth, g_Woth); cudaGetSymbolAddress((void**)&Wotl, g_Wotl);
    cudaGetSymbolAddress((void**)&Qh, g_Qh);   cudaGetSymbolAddress((void**)&Ql, g_Ql);
    cudaGetSymbolAddress((void**)&Kh, g_Kh);   cudaGetSymbolAddress((void**)&Kl, g_Kl);
    cudaGetSymbolAddress((void**)&Vth, g_Vth); cudaGetSymbolAddress((void**)&Vtl, g_Vtl);
    cudaGetSymbolAddress((void**)&Ph, g_Ph);   cudaGetSymbolAddress((void**)&Pl, g_Pl);
    cudaGetSymbolAddress((void**)&Zh, g_Zh);   cudaGetSymbolAddress((void**)&Zl, g_Zl);

    cudaFuncSetAttribute(mma_gemm, cudaFuncAttributeMaxDynamicSharedMemorySize, SMEM_DYN);

    const dim3 tb32x8(32, 8);

    // 1) build X (gather + transpose + PE) with fused hi/lo split
    build_x_kernel<<<dim3(DEMB / 32, SEQ / 32, BATCH), tb32x8>>>(ref_img, hdmap, X, Xh, Xl);

    // 2) weight transpose + split: w_q/k/v -> rows of Wqkvt [6144, 8192]; w_o -> Wot
    tsplit_kernel<<<dim3(QKVDIM / 32, DEMB / 32, 1), tb32x8>>>(
        w_q, 0, 0, QKVDIM, Wqkvth, Wqkvtl, 0, 0, DEMB, 1);
    tsplit_kernel<<<dim3(QKVDIM / 32, DEMB / 32, 1), tb32x8>>>(
        w_k, 0, 0, QKVDIM, Wqkvth + (long)QKVDIM * DEMB, Wqkvtl + (long)QKVDIM * DEMB, 0, 0, DEMB, 1);
    tsplit_kernel<<<dim3(QKVDIM / 32, DEMB / 32, 1), tb32x8>>>(
        w_v, 0, 0, QKVDIM, Wqkvth + (long)2 * QKVDIM * DEMB, Wqkvtl + (long)2 * QKVDIM * DEMB, 0, 0, DEMB, 1);
    tsplit_kernel<<<dim3(DEMB / 32, QKVDIM / 32, 1), tb32x8>>>(
        w_o, 0, 0, DEMB, Woth, Wotl, 0, 0, QKVDIM, 1);

    // 3) fused QKV projection: [4096,8192] x [8192,6144], round-7 mainloop,
    //    epilogue routes seg0->Qh/Ql, seg1->Kh/Kl, seg2->V fp32
    mma_gemm<<<dim3(3 * QKVDIM / 128, TOK_TOTAL / 128, 1), 256, SMEM_DYN>>>(
        Xh, Xl, DEMB, 0, 0,
        Wqkvth, Wqkvtl, DEMB, 0, 0,
        V, Qh, Ql, Kh, Kl, QKVDIM, 0, 0,
        nullptr, DEMB, 1, 1.0f, 1);

    // 4) transpose+split V per head -> Vt[b,h,d,t]
    tsplit_kernel<<<dim3(DKV / 32, SEQ / 32, BATCH * NHEAD), tb32x8>>>(
        V, (long)SEQ * QKVDIM, DKV, QKVDIM,
        Vth, Vtl, (long)NHEAD * DKV * SEQ, (long)DKV * SEQ, SEQ, NHEAD);

    // 5) scores S = (1/16) Q K^T per (b,h)
    const long sQKo = (long)SEQ * QKVDIM;
    const long sSo  = (long)NHEAD * SEQ * SEQ;
    mma_gemm<<<dim3(SEQ / 128, SEQ / 128, BATCH * NHEAD), 256, SMEM_DYN>>>(
        Qh, Ql, QKVDIM, sQKo, DKV,
        Kh, Kl, QKVDIM, sQKo, DKV,
        S, nullptr, nullptr, nullptr, nullptr, SEQ, sSo, (long)SEQ * SEQ,
        nullptr, DKV, NHEAD, 0.0625f, 0);

    // 6) softmax with fused P split
    softmax_kernel<<<BATCH * NHEAD * SEQ, 256>>>(S, Ph, Pl);

    // 7) Z = P @ V per (b,h), writes Zh/Zl directly
    mma_gemm<<<dim3(DKV / 128, SEQ / 128, BATCH * NHEAD), 256, SMEM_DYN>>>(
        Ph, Pl, SEQ, sSo, (long)SEQ * SEQ,
        Vth, Vtl, SEQ, (long)NHEAD * DKV * SEQ, (long)DKV * SEQ,
        nullptr, Zh, Zl, nullptr, nullptr, QKVDIM, sQKo, DKV,
        nullptr, SEQ, NHEAD, 1.0f, 0);

    // 8) O = Z @ w_o + X (residual)
    mma_gemm<<<dim3(DEMB / 128, TOK_TOTAL / 128, 1), 256, SMEM_DYN>>>(
        Zh, Zl, QKVDIM, 0, 0, Woth, Wotl, QKVDIM, 0, 0,
        O, nullptr, nullptr, nullptr, nullptr, DEMB, 0, 0,
        X, QKVDIM, 1, 1.0f, 0);

    // 9) LayerNorm stats + normalize/transpose out
    reduce_partial_kernel<<<dim3(1024, BATCH), 256>>>(O, part);
    finalize_stats_kernel<<<BATCH, 256>>>(part);
    ln_out_kernel<<<dim3(32, 32, BATCH * NHEAD), tb32x8>>>(O, gamma, beta, out);
}

// round 12
// speedup vs baseline: 2.8447x; 1.0534x over previous
#include <cuda_runtime.h>
#include <cuda_bf16.h>
#include <cstdint>
#include <math.h>

// ---------------------------------------------------------------------------
// Problem constants
// ---------------------------------------------------------------------------
#define BATCH      4
#define SEQ        1024
#define DEMB       8192
#define NHEAD      8
#define DKV        256
#define QKVDIM     (NHEAD * DKV)          // 2048
#define TOK_TOTAL  (BATCH * SEQ)          // 4096
#define PLANE      ((long)SEQ * DEMB)

// ---------------------------------------------------------------------------
// Scratch (static device allocations — no cudaMalloc allowed)
// ---------------------------------------------------------------------------
__device__ __align__(256) float  g_V[(long)BATCH * SEQ * QKVDIM];
__device__ __align__(256) float  g_S[(long)BATCH * NHEAD * SEQ * SEQ];
__device__ __align__(256) float  g_O[(long)BATCH * SEQ * DEMB];
__device__ double g_part[2048 * 2];       // per-CTA (sum, sumsq) from O-proj
__device__ double g_mean[BATCH];
__device__ double g_rstd[BATCH];

__device__ __align__(256) __nv_bfloat16 g_Xh[(long)BATCH * SEQ * DEMB];
__device__ __align__(256) __nv_bfloat16 g_Xl[(long)BATCH * SEQ * DEMB];
__device__ __align__(256) __nv_bfloat16 g_Wqkvth[(long)3 * QKVDIM * DEMB];
__device__ __align__(256) __nv_bfloat16 g_Wqkvtl[(long)3 * QKVDIM * DEMB];
__device__ __align__(256) __nv_bfloat16 g_Woth[(long)DEMB * QKVDIM];
__device__ __align__(256) __nv_bfloat16 g_Wotl[(long)DEMB * QKVDIM];
__device__ __align__(256) __nv_bfloat16 g_Qh[(long)BATCH * SEQ * QKVDIM];
__device__ __align__(256) __nv_bfloat16 g_Ql[(long)BATCH * SEQ * QKVDIM];
__device__ __align__(256) __nv_bfloat16 g_Kh[(long)BATCH * SEQ * QKVDIM];
__device__ __align__(256) __nv_bfloat16 g_Kl[(long)BATCH * SEQ * QKVDIM];
__device__ __align__(256) __nv_bfloat16 g_Vth[(long)BATCH * NHEAD * DKV * SEQ];
__device__ __align__(256) __nv_bfloat16 g_Vtl[(long)BATCH * NHEAD * DKV * SEQ];
__device__ __align__(256) __nv_bfloat16 g_Ph[(long)BATCH * NHEAD * SEQ * SEQ];
__device__ __align__(256) __nv_bfloat16 g_Pl[(long)BATCH * NHEAD * SEQ * SEQ];
__device__ __align__(256) __nv_bfloat16 g_Zh[(long)BATCH * SEQ * QKVDIM];
__device__ __align__(256) __nv_bfloat16 g_Zl[(long)BATCH * SEQ * QKVDIM];

// ---------------------------------------------------------------------------
// PTX helpers (sm_80-compatible: cp.async, ldmatrix, mma.sync)
// ---------------------------------------------------------------------------
__device__ __forceinline__ uint32_t smem_u32(const void* p) {
    uint32_t a;
    asm("{ .reg .u64 t; cvta.to.shared.u64 t, %1; cvt.u32.u64 %0, t; }"
        : "=r"(a) : "l"(p));
    return a;
}
__device__ __forceinline__ void cpasync16(uint32_t dst, const void* src) {
    asm volatile("cp.async.cg.shared.global [%0], [%1], 16;" :: "r"(dst), "l"(src));
}
__device__ __forceinline__ void cp_commit() {
    asm volatile("cp.async.commit_group;" ::: "memory");
}
template <int N> __device__ __forceinline__ void cp_wait() {
    asm volatile("cp.async.wait_group %0;" :: "n"(N) : "memory");
}
__device__ __forceinline__ void ldsm4(uint32_t* r, uint32_t addr) {
    asm volatile("ldmatrix.sync.aligned.m8n8.x4.shared.b16 {%0,%1,%2,%3}, [%4];"
                 : "=r"(r[0]), "=r"(r[1]), "=r"(r[2]), "=r"(r[3]) : "r"(addr));
}
__device__ __forceinline__ void ldsm2(uint32_t* r, uint32_t addr) {
    asm volatile("ldmatrix.sync.aligned.m8n8.x2.shared.b16 {%0,%1}, [%2];"
                 : "=r"(r[0]), "=r"(r[1]) : "r"(addr));
}
__device__ __forceinline__ void mma16816(float* c, const uint32_t* a, const uint32_t* b) {
    asm volatile(
        "mma.sync.aligned.m16n8k16.row.col.f32.bf16.bf16.f32 "
        "{%0,%1,%2,%3}, {%4,%5,%6,%7}, {%8,%9}, {%0,%1,%2,%3};"
        : "+f"(c[0]), "+f"(c[1]), "+f"(c[2]), "+f"(c[3])
        : "r"(a[0]), "r"(a[1]), "r"(a[2]), "r"(a[3]), "r"(b[0]), "r"(b[1]));
}
__device__ __forceinline__ __nv_bfloat162 split_hi2(float x, float y) {
    __nv_bfloat162 h;
    h.x = __float2bfloat16(x); h.y = __float2bfloat16(y);
    return h;
}
__device__ __forceinline__ __nv_bfloat162 split_lo2(float x, float y, __nv_bfloat162 h) {
    __nv_bfloat162 l;
    l.x = __float2bfloat16(x - __bfloat162float(h.x));
    l.y = __float2bfloat16(y - __bfloat162float(h.y));
    return l;
}

// ---------------------------------------------------------------------------
// Split-precision bf16 GEMM on mma.sync (round-7/11 proven config).
// acc = alpha * (Ah*Bh^T + Ah*Bl^T + Al*Bh^T) (+ (Dh+Dl) residual), fp32 accum.
// Tile 128x128, K-chunk 64, 3-stage cp.async pipeline, XOR-swizzled smem.
// mode 0: outputs Cf (fp32) and/or Ch/Cl (bf16 hi/lo).
// mode 1 (fused QKV): column segment seg=col0>>11 routes to
//         seg0 -> Ch/Cl (Q), seg1 -> C2h/C2l (K), seg2 -> Cf (V fp32); ldc=2048.
// doLN: per-CTA fp64 (sum,sumsq) of outputs -> g_part[pid_m*gridDim.x + pid_n].
// Batch z: offset = (z/inner)*so + (z%inner)*si per operand.
// ---------------------------------------------------------------------------
#define KC      64
#define TILE_B  16384                     // 128 rows x 128 bytes
#define STG_B   (4 * TILE_B)              // Ah, Al, Bh, Bl per stage
#define NSTAGE  3
#define SMEM_DYN (NSTAGE * STG_B)         // 196608

__global__ __launch_bounds__(256, 1)
void mma_gemm(const __nv_bfloat16* __restrict__ Ah, const __nv_bfloat16* __restrict__ Al,
              int lda, long sAo, long sAi,
              const __nv_bfloat16* __restrict__ Bh, const __nv_bfloat16* __restrict__ Bl,
              int ldb, long sBo, long sBi,
              float* __restrict__ Cf,
              __nv_bfloat16* __restrict__ Ch, __nv_bfloat16* __restrict__ Cl,
              __nv_bfloat16* __restrict__ C2h, __nv_bfloat16* __restrict__ C2l,
              int ldc, long sCo, long sCi,
              const __nv_bfloat16* __restrict__ Dh, const __nv_bfloat16* __restrict__ Dl,
              int K, int inner, float alpha, int mode, int doLN)
{
    extern __shared__ __align__(128) char dsm_raw[];
    const uint32_t dsm0 = smem_u32(dsm_raw);

    const int tid  = threadIdx.x;
    const int lane = tid & 31;
    const int wid  = tid >> 5;
    const int wm   = wid & 1;             // warp row (2)
    const int wn   = wid >> 1;            // warp col (4)

    const int z  = blockIdx.z;
    const int zo = z / inner, zi = z - zo * inner;
    Ah += zo * sAo + zi * sAi;  Al += zo * sAo + zi * sAi;
    Bh += zo * sBo + zi * sBi;  Bl += zo * sBo + zi * sBi;
    const long coff = zo * sCo + zi * sCi;

    // grouped rasterization: GROUP M-tiles per stripe, sweep N within stripe
    int pid_m, pid_n;
    {
        const int ntm = gridDim.y, ntn = gridDim.x;
        const int lin = blockIdx.y * ntn + blockIdx.x;
        const int G = 8;
        const int width = G * ntn;
        const int grp = lin / width;
        const int rem = lin - grp * width;
        const int m0  = grp * G;
        const int gsz = (ntm - m0 < G) ? (ntm - m0) : G;
        pid_m = m0 + rem % gsz;
        pid_n = rem / gsz;
    }
    const int row0 = pid_m * 128;
    const int col0 = pid_n * 128;

    // cp.async geometry: 1024 16B-chunks per tile; 4 per thread per tile
    int rr[4], cc[4]; uint32_t swo[4];
    #pragma unroll
    for (int j = 0; j < 4; j++) {
        int idx = tid + j * 256;
        rr[j] = idx >> 3;
        cc[j] = idx & 7;
        swo[j] = (uint32_t)(rr[j] * 128 + ((cc[j] ^ (rr[j] & 7)) << 4));
    }
    const __nv_bfloat16* tp[4] = {Ah, Al, Bh, Bl};
    const int nk = K / KC;

    auto load_stage = [&](int s, int k0) {
        const uint32_t sb = dsm0 + s * STG_B;
        #pragma unroll
        for (int t = 0; t < 4; t++) {
            const __nv_bfloat16* g = tp[t];
            const long ld = (t < 2) ? lda : ldb;
            const int  rb = (t < 2) ? row0 : col0;
            const uint32_t tb = sb + t * TILE_B;
            #pragma unroll
            for (int j = 0; j < 4; j++)
                cpasync16(tb + swo[j], g + (long)(rb + rr[j]) * ld + k0 + cc[j] * 8);
        }
        cp_commit();
    };

    // ldmatrix lane geometry
    const int l7   = lane & 7;
    const int aRow = wm * 64 + l7 + ((lane >> 3) & 1) * 8;
    const int aSel = (lane >> 4) & 1;
    const int bRow = wn * 32 + l7;
    const int bSel = (lane >> 3) & 1;
    const uint32_t aRowOff = (uint32_t)aRow * 128;
    const uint32_t bRowOff = (uint32_t)bRow * 128;

    float acc[4][4][4];
    #pragma unroll
    for (int mt = 0; mt < 4; mt++)
        #pragma unroll
        for (int nt = 0; nt < 4; nt++)
            #pragma unroll
            for (int q = 0; q < 4; q++) acc[mt][nt][q] = 0.f;

    load_stage(0, 0);
    load_stage(1, KC);

    for (int i = 0; i < nk; ++i) {
        const int s = i % NSTAGE;
        if (i + 1 < nk) cp_wait<1>(); else cp_wait<0>();
        __syncthreads();
        if (i + 2 < nk) load_stage((i + 2) % NSTAGE, (i + 2) * KC);

        const uint32_t sb = dsm0 + s * STG_B;
        #pragma unroll
        for (int ks = 0; ks < 4; ++ks) {
            uint32_t ah[4][4], al[4][4], bh[4][2], bl[4][2];
            const uint32_t asw = (uint32_t)(((2 * ks + aSel) ^ l7) << 4);
            const uint32_t bsw = (uint32_t)(((2 * ks + bSel) ^ l7) << 4);
            #pragma unroll
            for (int mt = 0; mt < 4; mt++) {
                uint32_t ad = sb + aRowOff + mt * 2048 + asw;
                ldsm4(ah[mt], ad);
                ldsm4(al[mt], ad + TILE_B);
            }
            #pragma unroll
            for (int nt = 0; nt < 4; nt++) {
                uint32_t bd = sb + 2 * TILE_B + bRowOff + nt * 1024 + bsw;
                ldsm2(bh[nt], bd);
                ldsm2(bl[nt], bd + TILE_B);
            }
            #pragma unroll
            for (int mt = 0; mt < 4; mt++)
                #pragma unroll
                for (int nt = 0; nt < 4; nt++) {
                    mma16816(acc[mt][nt], ah[mt], bh[nt]);
                    mma16816(acc[mt][nt], ah[mt], bl[nt]);
                    mma16816(acc[mt][nt], al[mt], bh[nt]);
                }
        }
        __syncthreads();
    }

    // ---- epilogue: mode-based routing
    float* cf = Cf;
    __nv_bfloat16 *ch = Ch, *cl = Cl;
    int cbase = col0;
    if (mode) {
        const int seg = col0 >> 11;
        cbase = col0 & 2047;
        if (seg == 0)      { cf = nullptr; ch = Ch;  cl = Cl;  }
        else if (seg == 1) { cf = nullptr; ch = C2h; cl = C2l; }
        else               { ch = nullptr; cl = nullptr; }
    }
    if (cf) cf += coff;
    if (ch) { ch += coff; cl += coff; }
    const __nv_bfloat16* dh = Dh ? (Dh + coff) : (const __nv_bfloat16*)0;
    const __nv_bfloat16* dl = Dh ? (Dl + coff) : (const __nv_bfloat16*)0;

    float lnS = 0.f, lnS2 = 0.f;
    const int cg = lane >> 2, tg = lane & 3;
    #pragma unroll
    for (int mt = 0; mt < 4; mt++) {
        #pragma unroll
        for (int nt = 0; nt < 4; nt++) {
            const int r = row0 + wm * 64 + mt * 16 + cg;
            const int c = cbase + wn * 32 + nt * 8 + tg * 2;
            const long o0 = (long)r * ldc + c;
            const long o1 = (long)(r + 8) * ldc + c;
            float2 v0, v1;
            v0.x = acc[mt][nt][0] * alpha; v0.y = acc[mt][nt][1] * alpha;
            v1.x = acc[mt][nt][2] * alpha; v1.y = acc[mt][nt][3] * alpha;
            if (dh) {
                __nv_bfloat162 h0 = *(const __nv_bfloat162*)(dh + o0);
                __nv_bfloat162 l0 = *(const __nv_bfloat162*)(dl + o0);
                __nv_bfloat162 h1 = *(const __nv_bfloat162*)(dh + o1);
                __nv_bfloat162 l1 = *(const __nv_bfloat162*)(dl + o1);
                v0.x += __bfloat162float(h0.x) + __bfloat162float(l0.x);
                v0.y += __bfloat162float(h0.y) + __bfloat162float(l0.y);
                v1.x += __bfloat162float(h1.x) + __bfloat162float(l1.x);
                v1.y += __bfloat162float(h1.y) + __bfloat162float(l1.y);
            }
            if (doLN) {
                lnS  += v0.x + v0.y + v1.x + v1.y;
                lnS2 += v0.x * v0.x + v0.y * v0.y + v1.x * v1.x + v1.y * v1.y;
            }
            if (cf) {
                *(float2*)(cf + o0) = v0;
                *(float2*)(cf + o1) = v1;
            }
            if (ch) {
                __nv_bfloat162 h0 = split_hi2(v0.x, v0.y);
                __nv_bfloat162 h1 = split_hi2(v1.x, v1.y);
                *(__nv_bfloat162*)(ch + o0) = h0;
                *(__nv_bfloat162*)(ch + o1) = h1;
                *(__nv_bfloat162*)(cl + o0) = split_lo2(v0.x, v0.y, h0);
                *(__nv_bfloat162*)(cl + o1) = split_lo2(v1.x, v1.y, h1);
            }
        }
    }

    if (doLN) {
        // per-CTA deterministic (sum, sumsq): fp32 per-thread -> fp64 smem tree
        double* shd = (double*)dsm_raw;
        shd[tid]       = (double)lnS;
        shd[256 + tid] = (double)lnS2;
        __syncthreads();
        for (int o = 128; o; o >>= 1) {
            if (tid < o) {
                shd[tid]       += shd[tid + o];
                shd[256 + tid] += shd[256 + tid + o];
            }
            __syncthreads();
        }
        if (tid == 0) {
            const int idx = pid_m * gridDim.x + pid_n;
            g_part[idx * 2 + 0] = shd[0];
            g_part[idx * 2 + 1] = shd[256];
        }
    }
}

// ---------------------------------------------------------------------------
// fp32 [R,C] -> bf16 hi/lo transposed [C,R]  (batched via strides)
// ---------------------------------------------------------------------------
__global__ void tsplit_kernel(const float* __restrict__ in, long sIo, long sIi, int ldin,
                              __nv_bfloat16* __restrict__ hi, __nv_bfloat16* __restrict__ lo,
                              long sOo, long sOi, int ldo, int inner)
{
    __shared__ float tile[32][33];
    const int z = blockIdx.z, zo = z / inner, zi = z - zo * inner;
    in += zo * sIo + zi * sIi;
    hi += zo * sOo + zi * sOi;
    lo += zo * sOo + zi * sOi;
    const int r0 = blockIdx.y * 32, c0 = blockIdx.x * 32;
    const int tx = threadIdx.x, ty = threadIdx.y;
    #pragma unroll
    for (int i = 0; i < 4; i++)
        tile[ty + i * 8][tx] = in[(long)(r0 + ty + i * 8) * ldin + c0 + tx];
    __syncthreads();
    const int t  = ty * 32 + tx;
    const int rp = t & 15;
    const int cb = t >> 4;
    #pragma unroll
    for (int pass = 0; pass < 2; pass++) {
        const int cl_ = cb + pass * 16;
        const float v0 = tile[2 * rp][cl_];
        const float v1 = tile[2 * rp + 1][cl_];
        __nv_bfloat162 h = split_hi2(v0, v1);
        const long o = (long)(c0 + cl_) * ldo + r0 + 2 * rp;
        *(__nv_bfloat162*)(hi + o) = h;
        *(__nv_bfloat162*)(lo + o) = split_lo2(v0, v1, h);
    }
}

// ---------------------------------------------------------------------------
// Merged Q/K/V weight transpose+split: z selects source; dest = Wqkvt + z*seg
// ---------------------------------------------------------------------------
__global__ void qkv_tsplit_kernel(const float* __restrict__ wq,
                                  const float* __restrict__ wk,
                                  const float* __restrict__ wv,
                                  __nv_bfloat16* __restrict__ hi,
                                  __nv_bfloat16* __restrict__ lo)
{
    __shared__ float tile[32][33];
    const int z = blockIdx.z;
    const float* in = (z == 0) ? wq : (z == 1) ? wk : wv;
    hi += (long)z * QKVDIM * DEMB;
    lo += (long)z * QKVDIM * DEMB;
    const int r0 = blockIdx.y * 32, c0 = blockIdx.x * 32;
    const int tx = threadIdx.x, ty = threadIdx.y;
    #pragma unroll
    for (int i = 0; i < 4; i++)
        tile[ty + i * 8][tx] = in[(long)(r0 + ty + i * 8) * QKVDIM + c0 + tx];
    __syncthreads();
    const int t  = ty * 32 + tx;
    const int rp = t & 15;
    const int cb = t >> 4;
    #pragma unroll
    for (int pass = 0; pass < 2; pass++) {
        const int cl_ = cb + pass * 16;
        const float v0 = tile[2 * rp][cl_];
        const float v1 = tile[2 * rp + 1][cl_];
        __nv_bfloat162 h = split_hi2(v0, v1);
        const long o = (long)(c0 + cl_) * DEMB + r0 + 2 * rp;
        *(__nv_bfloat162*)(hi + o) = h;
        *(__nv_bfloat162*)(lo + o) = split_lo2(v0, v1, h);
    }
}

// ---------------------------------------------------------------------------
// build X (gather + transpose + PE) writing bf16 hi/lo only
// ---------------------------------------------------------------------------
__global__ void build_x_kernel(const float* __restrict__ ref,
                               const float* __restrict__ hd,
                               __nv_bfloat16* __restrict__ Xh,
                               __nv_bfloat16* __restrict__ Xl)
{
    __shared__ float tile[32][33];
    const int b  = blockIdx.z;
    const int f0 = blockIdx.x * 32;
    const int t0 = blockIdx.y * 32;
    const int tx = threadIdx.x, ty = threadIdx.y;

#pragma unroll
    for (int i = 0; i < 4; i++) {
        int f  = f0 + ty + i * 8;
        int n_ = f >> 10;
        int s  = f & 1023;
        int hh = s >> 5;
        int ww = s & 31;
        const float* src = (ww < 16)
            ? ref + ((long)(((b * 8 + n_) * 32 + hh) * 16 + ww)) * 1024
            : hd  + ((long)(((b * 8 + n_) * 32 + hh) * 16 + (ww - 16))) * 1024;
        tile[ty + i * 8][tx] = src[t0 + tx];
    }
    __syncthreads();
#pragma unroll
    for (int i = 0; i < 4; i++) {
        int t = t0 + ty + i * 8;
        int f = f0 + tx;
        float freq = __expf((float)f * (-9.210340371976184f / 4096.0f));
        float ang  = (float)t * freq;
        float pe   = (f & 1) ? cosf(ang) : sinf(ang);
        float v    = tile[tx][ty + i * 8] + 0.001f * pe;
        long  o    = (long)b * PLANE + (long)t * DEMB + f;
        __nv_bfloat16 h = __float2bfloat16(v);
        Xh[o] = h;
        Xl[o] = __float2bfloat16(v - __bfloat162float(h));
    }
}

// ---------------------------------------------------------------------------
// Softmax over rows of S, writing bf16 hi/lo P directly.
// ---------------------------------------------------------------------------
__global__ void softmax_kernel(const float* __restrict__ S,
                               __nv_bfloat16* __restrict__ Ph,
                               __nv_bfloat16* __restrict__ Pl)
{
    __shared__ float red[8];
    const int tid  = threadIdx.x;
    const int lane = tid & 31, warp = tid >> 5;
    const float4* row = (const float4*)(S + (long)blockIdx.x * SEQ);
    float4 v = row[tid];

    float m = fmaxf(fmaxf(v.x, v.y), fmaxf(v.z, v.w));
#pragma unroll
    for (int o = 16; o; o >>= 1) m = fmaxf(m, __shfl_xor_sync(~0u, m, o));
    if (lane == 0) red[warp] = m;
    __syncthreads();
    float M = red[0];
#pragma unroll
    for (int i = 1; i < 8; i++) M = fmaxf(M, red[i]);

    v.x = __expf(v.x - M); v.y = __expf(v.y - M);
    v.z = __expf(v.z - M); v.w = __expf(v.w - M);
    float s = v.x + v.y + v.z + v.w;
#pragma unroll
    for (int o = 16; o; o >>= 1) s += __shfl_xor_sync(~0u, s, o);
    __syncthreads();
    if (lane == 0) red[warp] = s;
    __syncthreads();
    float T = 0.f;
#pragma unroll
    for (int i = 0; i < 8; i++) T += red[i];
    float inv = 1.0f / T;
    v.x *= inv; v.y *= inv; v.z *= inv; v.w *= inv;

    const long o = (long)blockIdx.x * SEQ + tid * 4;
    __nv_bfloat162 h0 = split_hi2(v.x, v.y);
    __nv_bfloat162 h1 = split_hi2(v.z, v.w);
    *(__nv_bfloat162*)(Ph + o)     = h0;
    *(__nv_bfloat162*)(Ph + o + 2) = h1;
    *(__nv_bfloat162*)(Pl + o)     = split_lo2(v.x, v.y, h0);
    *(__nv_bfloat162*)(Pl + o + 2) = split_lo2(v.z, v.w, h1);
}

// ---------------------------------------------------------------------------
// LayerNorm finalize (reads per-CTA partials from O-proj) + output transform
// ---------------------------------------------------------------------------
__global__ void finalize_stats_kernel()
{
    __shared__ double sh[256], sh2[256];
    const int b = blockIdx.x, tid = threadIdx.x;
    double s = 0.0, s2 = 0.0;
    for (int i = tid; i < 512; i += 256) {
        s  += g_part[(b * 512 + i) * 2 + 0];
        s2 += g_part[(b * 512 + i) * 2 + 1];
    }
    sh[tid] = s; sh2[tid] = s2;
    __syncthreads();
    for (int o = 128; o; o >>= 1) {
        if (tid < o) { sh[tid] += sh[tid + o]; sh2[tid] += sh2[tid + o]; }
        __syncthreads();
    }
    if (tid == 0) {
        double n    = (double)PLANE;
        double mean = sh[0] / n;
        double var  = sh2[0] / n - mean * mean;
        g_mean[b] = mean;
        g_rstd[b] = rsqrt(var + 1e-6);
    }
}

__global__ void ln_out_kernel(const float* __restrict__ O,
                              const float* __restrict__ gamma,
                              const float* __restrict__ beta,
                              float* __restrict__ out)
{
    __shared__ float tile[32][33];
    const int bz = blockIdx.z;
    const int b  = bz >> 3;
    const int nf = (bz & 7) * 1024;
    const int c0 = blockIdx.x * 32;
    const int t0 = blockIdx.y * 32;
    const int tx = threadIdx.x, ty = threadIdx.y;
    const float mean = (float)g_mean[b];
    const float rstd = (float)g_rstd[b];

#pragma unroll
    for (int i = 0; i < 4; i++) {
        int t   = t0 + ty + i * 8;
        long fi = (long)t * DEMB + nf + c0 + tx;
        float v = O[(long)b * PLANE + fi];
        tile[ty + i * 8][tx] = (v - mean) * rstd * gamma[fi] + beta[fi];
    }
    __syncthreads();
#pragma unroll
    for (int i = 0; i < 4; i++) {
        int c = c0 + ty + i * 8;
        out[((long)bz * 1024 + c) * 1024 + t0 + tx] = tile[tx][ty + i * 8];
    }
}

// ---------------------------------------------------------------------------
// Launcher
// ---------------------------------------------------------------------------
extern "C" void kernel_launch(void* const* d_in, const int* in_sizes, int n_in,
                              void* d_out, int out_size)
{
    const float* ref_img = (const float*)d_in[0];
    const float* hdmap   = (const float*)d_in[1];
    const float* w_q     = (const float*)d_in[2];
    const float* w_k     = (const float*)d_in[3];
    const float* w_v     = (const float*)d_in[4];
    const float* w_o     = (const float*)d_in[5];
    const float* gamma   = (const float*)d_in[6];
    const float* beta    = (const float*)d_in[7];
    float* out = (float*)d_out;

    float *V, *S, *O;
    __nv_bfloat16 *Xh, *Xl, *Wqkvth, *Wqkvtl, *Woth, *Wotl;
    __nv_bfloat16 *Qh, *Ql, *Kh, *Kl, *Vth, *Vtl, *Ph, *Pl, *Zh, *Zl;
    cudaGetSymbolAddress((void**)&V, g_V);
    cudaGetSymbolAddress((void**)&S, g_S);     cudaGetSymbolAddress((void**)&O, g_O);
    cudaGetSymbolAddress((void**)&Xh, g_Xh);   cudaGetSymbolAddress((void**)&Xl, g_Xl);
    cudaGetSymbolAddress((void**)&Wqkvth, g_Wqkvth);
    cudaGetSymbolAddress((void**)&Wqkvtl, g_Wqkvtl);
    cudaGetSymbolAddress((void**)&Woth, g_Woth); cudaGetSymbolAddress((void**)&Wotl, g_Wotl);
    cudaGetSymbolAddress((void**)&Qh, g_Qh);   cudaGetSymbolAddress((void**)&Ql, g_Ql);
    cudaGetSymbolAddress((void**)&Kh, g_Kh);   cudaGetSymbolAddress((void**)&Kl, g_Kl);
    cudaGetSymbolAddress((void**)&Vth, g_Vth); cudaGetSymbolAddress((void**)&Vtl, g_Vtl);
    cudaGetSymbolAddress((void**)&Ph, g_Ph);   cudaGetSymbolAddress((void**)&Pl, g_Pl);
    cudaGetSymbolAddress((void**)&Zh, g_Zh);   cudaGetSymbolAddress((void**)&Zl, g_Zl);

    cudaFuncSetAttribute(mma_gemm, cudaFuncAttributeMaxDynamicSharedMemorySize, SMEM_DYN);

    const dim3 tb32x8(32, 8);

    // 1) build X (gather + transpose + PE) with fused hi/lo split (no fp32 X)
    build_x_kernel<<<dim3(DEMB / 32, SEQ / 32, BATCH), tb32x8>>>(ref_img, hdmap, Xh, Xl);

    // 2) weight transpose + split: merged q/k/v -> Wqkvt [6144, 8192]; w_o -> Wot
    qkv_tsplit_kernel<<<dim3(QKVDIM / 32, DEMB / 32, 3), tb32x8>>>(
        w_q, w_k, w_v, Wqkvth, Wqkvtl);
    tsplit_kernel<<<dim3(DEMB / 32, QKVDIM / 32, 1), tb32x8>>>(
        w_o, 0, 0, DEMB, Woth, Wotl, 0, 0, QKVDIM, 1);

    // 3) fused QKV projection: [4096,8192] x [8192,6144]
    mma_gemm<<<dim3(3 * QKVDIM / 128, TOK_TOTAL / 128, 1), 256, SMEM_DYN>>>(
        Xh, Xl, DEMB, 0, 0,
        Wqkvth, Wqkvtl, DEMB, 0, 0,
        V, Qh, Ql, Kh, Kl, QKVDIM, 0, 0,
        nullptr, nullptr, DEMB, 1, 1.0f, 1, 0);

    // 4) transpose+split V per head -> Vt[b,h,d,t]
    tsplit_kernel<<<dim3(DKV / 32, SEQ / 32, BATCH * NHEAD), tb32x8>>>(
        V, (long)SEQ * QKVDIM, DKV, QKVDIM,
        Vth, Vtl, (long)NHEAD * DKV * SEQ, (long)DKV * SEQ, SEQ, NHEAD);

    // 5) scores S = (1/16) Q K^T per (b,h)
    const long sQKo = (long)SEQ * QKVDIM;
    const long sSo  = (long)NHEAD * SEQ * SEQ;
    mma_gemm<<<dim3(SEQ / 128, SEQ / 128, BATCH * NHEAD), 256, SMEM_DYN>>>(
        Qh, Ql, QKVDIM, sQKo, DKV,
        Kh, Kl, QKVDIM, sQKo, DKV,
        S, nullptr, nullptr, nullptr, nullptr, SEQ, sSo, (long)SEQ * SEQ,
        nullptr, nullptr, DKV, NHEAD, 0.0625f, 0, 0);

    // 6) softmax with fused P split
    softmax_kernel<<<BATCH * NHEAD * SEQ, 256>>>(S, Ph, Pl);

    // 7) Z = P @ V per (b,h), writes Zh/Zl directly
    mma_gemm<<<dim3(DKV / 128, SEQ / 128, BATCH * NHEAD), 256, SMEM_DYN>>>(
        Ph, Pl, SEQ, sSo, (long)SEQ * SEQ,
        Vth, Vtl, SEQ, (long)NHEAD * DKV * SEQ, (long)DKV * SEQ,
        nullptr, Zh, Zl, nullptr, nullptr, QKVDIM, sQKo, DKV,
        nullptr, nullptr, SEQ, NHEAD, 1.0f, 0, 0);

    // 8) O = Z @ w_o + (Xh+Xl) residual; fused LN partial stats per CTA
    mma_gemm<<<dim3(DEMB / 128, TOK_TOTAL / 128, 1), 256, SMEM_DYN>>>(
        Zh, Zl, QKVDIM, 0, 0, Woth, Wotl, QKVDIM, 0, 0,
        O, nullptr, nullptr, nullptr, nullptr, DEMB, 0, 0,
        Xh, Xl, QKVDIM, 1, 1.0f, 0, 1);

    // 9) LayerNorm finalize + normalize/transpose out
    finalize_stats_kernel<<<BATCH, 256>>>();
    ln_out_kernel<<<dim3(32, 32, BATCH * NHEAD), tb32x8>>>(O, gamma, beta, out);
}